// round 4
// baseline (speedup 1.0000x reference)
#include <cuda_runtime.h>
#include <math.h>

#define BATCH 256
#define C1_IN 3
#define C1_OUT 6
#define H_IN 250
#define C1_H 124          // conv1 out H/W
#define P1_H 123          // pool1 out H/W
#define C2_OUT 15
#define C2_H 62           // conv2 out H/W
#define P2_H 61           // pool2 out H/W
#define K_FC1 55815       // 15*61*61
#define N_FC1 120
#define N_FC2 84
#define KSPLIT 148
#define KCHUNK 378        // ceil(55815/148)

typedef unsigned long long ull;

// Scratch (static device globals — allocation-free)
__device__ float g_conv1[(size_t)BATCH * C1_OUT * C1_H * C1_H];   // 94.5 MB
__device__ float g_conv2[(size_t)BATCH * C2_OUT * C2_H * C2_H];   // 59 MB
__device__ float g_fc1_part[KSPLIT][BATCH * N_FC1];               // 18.2 MB

// packed f32x2 helpers
#define BPACK(dst, f) asm("mov.b64 %0, {%1, %1};" : "=l"(dst) : "r"(__float_as_uint(f)))
#define PACK2(dst, lo, hi) asm("mov.b64 %0, {%1, %2};" : "=l"(dst) : "r"(__float_as_uint(lo)), "r"(__float_as_uint(hi)))
#define FMA2(acc, a, b) asm("fma.rn.f32x2 %0, %1, %2, %0;" : "+l"(acc) : "l"(a), "l"(b))
#define LO(v) __uint_as_float((unsigned)((v) & 0xffffffffULL))
#define HI(v) __uint_as_float((unsigned)((v) >> 32))

// ---------------------------------------------------------------------------
// conv1: 3->6, 5x5, stride 2, pad 1, + ReLU. Block = 32x32 output tile.
// Thread computes 4 consecutive-x outputs for all 6 oc. Weights pre-packed
// as f32x2 pairs in smem; inputs loaded as 3x LDS.128 per (c,ky).
// smem: S[3][67][68] + Wp[450](ull) + Bias[6]
// ---------------------------------------------------------------------------
#define C1_PITCH 68
#define C1_ROWS 67
#define C1_S_ELEMS (3 * C1_ROWS * C1_PITCH)     // 13668
#define C1_SMEM_BYTES (C1_S_ELEMS * 4 + 450 * 8 + 64)

__global__ __launch_bounds__(256) void conv1_kernel(const float* __restrict__ x,
                                                    const float* __restrict__ w1,
                                                    const float* __restrict__ b1) {
    extern __shared__ float sm1[];
    float* S = sm1;                                   // [3][67][68]
    ull* Wp = (ull*)(sm1 + C1_S_ELEMS);               // [450]
    float* Bias = (float*)(Wp + 450);

    const int b = blockIdx.z;
    const int ox0 = blockIdx.x * 32, oy0 = blockIdx.y * 32;
    const int tid = threadIdx.x;

    for (int i = tid; i < 450; i += 256) { ull p; BPACK(p, w1[i]); Wp[i] = p; }
    if (tid < 6) Bias[tid] = b1[tid];

    const int iy0 = oy0 * 2 - 1, ix0 = ox0 * 2 - 1;
    const float* xb = x + (size_t)b * C1_IN * H_IN * H_IN;

    for (int idx = tid; idx < C1_S_ELEMS; idx += 256) {
        int c = idx / (C1_ROWS * C1_PITCH), r = idx % (C1_ROWS * C1_PITCH);
        int y = r / C1_PITCH, u = r % C1_PITCH;
        int iy = iy0 + y, ix = ix0 + u;
        float v = 0.f;
        if (iy >= 0 && iy < H_IN && ix >= 0 && ix < H_IN)
            v = xb[(c * H_IN + iy) * H_IN + ix];
        S[idx] = v;
    }
    __syncthreads();

    const int row = tid >> 3;        // 0..31
    const int cg = tid & 7;          // 0..7, outputs ox0+cg*4 .. +3

    ull accA[6], accB[6];            // (px0,px1), (px2,px3)
#pragma unroll
    for (int oc = 0; oc < 6; oc++) { accA[oc] = 0ULL; accB[oc] = 0ULL; }

#pragma unroll
    for (int c = 0; c < 3; c++) {
        const float* Sc = S + c * C1_ROWS * C1_PITCH;
#pragma unroll
        for (int ky = 0; ky < 5; ky++) {
            const float* rp = Sc + (row * 2 + ky) * C1_PITCH + cg * 8;
            float4 v0 = *(const float4*)(rp);
            float4 v1 = *(const float4*)(rp + 4);
            float4 v2 = *(const float4*)(rp + 8);
            float v[12] = {v0.x, v0.y, v0.z, v0.w, v1.x, v1.y, v1.z, v1.w,
                           v2.x, v2.y, v2.z, v2.w};
#pragma unroll
            for (int kx = 0; kx < 5; kx++) {
                ull sA, sB;
                PACK2(sA, v[kx], v[kx + 2]);
                PACK2(sB, v[kx + 4], v[kx + 6]);
#pragma unroll
                for (int oc = 0; oc < 6; oc++) {
                    ull w = Wp[((oc * 3 + c) * 5 + ky) * 5 + kx];
                    FMA2(accA[oc], sA, w);
                    FMA2(accB[oc], sB, w);
                }
            }
        }
    }

    const int oy = oy0 + row;
    const int ox = ox0 + cg * 4;
    if (oy < C1_H) {
#pragma unroll
        for (int oc = 0; oc < 6; oc++) {
            float* dst = g_conv1 + ((size_t)(b * C1_OUT + oc) * C1_H + oy) * C1_H;
            float bias = Bias[oc];
            if (ox + 0 < C1_H) dst[ox + 0] = fmaxf(LO(accA[oc]) + bias, 0.f);
            if (ox + 1 < C1_H) dst[ox + 1] = fmaxf(HI(accA[oc]) + bias, 0.f);
            if (ox + 2 < C1_H) dst[ox + 2] = fmaxf(LO(accB[oc]) + bias, 0.f);
            if (ox + 3 < C1_H) dst[ox + 3] = fmaxf(HI(accB[oc]) + bias, 0.f);
        }
    }
}

// ---------------------------------------------------------------------------
// conv2: maxpool(2,s1) fused into smem load; 6->15, 3x3, stride 2, pad 1, ReLU
// Same register-blocked structure, 4 consecutive-x outputs x 15 oc.
// smem: P[6][65][68] + Wp[810](ull) + Bias[15]
// ---------------------------------------------------------------------------
#define C2_PITCH 68
#define C2_ROWS 65
#define C2_P_ELEMS (6 * C2_ROWS * C2_PITCH)     // 26520
#define C2_SMEM_BYTES (C2_P_ELEMS * 4 + 810 * 8 + 96)

__global__ __launch_bounds__(256) void conv2_kernel(const float* __restrict__ w2,
                                                    const float* __restrict__ b2) {
    extern __shared__ float sm2[];
    float* P = sm2;                                   // [6][65][68]
    ull* Wp = (ull*)(sm2 + C2_P_ELEMS);               // [810]
    float* Bias = (float*)(Wp + 810);

    const int b = blockIdx.z;
    const int ox0 = blockIdx.x * 32, oy0 = blockIdx.y * 32;
    const int tid = threadIdx.x;

    for (int i = tid; i < 810; i += 256) { ull p; BPACK(p, w2[i]); Wp[i] = p; }
    if (tid < 15) Bias[tid] = b2[tid];

    const int py0 = oy0 * 2 - 1, px0 = ox0 * 2 - 1;
    const float* cb = g_conv1 + (size_t)b * C1_OUT * C1_H * C1_H;

    for (int idx = tid; idx < C2_P_ELEMS; idx += 256) {
        int c = idx / (C2_ROWS * C2_PITCH), r = idx % (C2_ROWS * C2_PITCH);
        int y = r / C2_PITCH, u = r % C2_PITCH;
        int py = py0 + y, px = px0 + u;
        float v = 0.f;
        if (py >= 0 && py < P1_H && px >= 0 && px < P1_H) {
            const float* p = cb + (c * C1_H + py) * C1_H + px;
            v = fmaxf(fmaxf(p[0], p[1]), fmaxf(p[C1_H], p[C1_H + 1]));
        }
        P[idx] = v;
    }
    __syncthreads();

    const int row = tid >> 3;
    const int cg = tid & 7;

    ull accA[15], accB[15];
#pragma unroll
    for (int oc = 0; oc < 15; oc++) { accA[oc] = 0ULL; accB[oc] = 0ULL; }

#pragma unroll
    for (int c = 0; c < 6; c++) {
        const float* Pc = P + c * C2_ROWS * C2_PITCH;
#pragma unroll
        for (int ky = 0; ky < 3; ky++) {
            const float* rp = Pc + (row * 2 + ky) * C2_PITCH + cg * 8;
            float4 v0 = *(const float4*)(rp);
            float4 v1 = *(const float4*)(rp + 4);
            float4 v2 = *(const float4*)(rp + 8);
            float v[12] = {v0.x, v0.y, v0.z, v0.w, v1.x, v1.y, v1.z, v1.w,
                           v2.x, v2.y, v2.z, v2.w};
#pragma unroll
            for (int kx = 0; kx < 3; kx++) {
                ull sA, sB;
                PACK2(sA, v[kx], v[kx + 2]);
                PACK2(sB, v[kx + 4], v[kx + 6]);
#pragma unroll
                for (int oc = 0; oc < 15; oc++) {
                    ull w = Wp[((oc * 6 + c) * 3 + ky) * 3 + kx];
                    FMA2(accA[oc], sA, w);
                    FMA2(accB[oc], sB, w);
                }
            }
        }
    }

    const int oy = oy0 + row;
    const int ox = ox0 + cg * 4;
    if (oy < C2_H) {
#pragma unroll
        for (int oc = 0; oc < 15; oc++) {
            float* dst = g_conv2 + ((size_t)(b * C2_OUT + oc) * C2_H + oy) * C2_H;
            float bias = Bias[oc];
            if (ox + 0 < C2_H) dst[ox + 0] = fmaxf(LO(accA[oc]) + bias, 0.f);
            if (ox + 1 < C2_H) dst[ox + 1] = fmaxf(HI(accA[oc]) + bias, 0.f);
            if (ox + 2 < C2_H) dst[ox + 2] = fmaxf(LO(accB[oc]) + bias, 0.f);
            if (ox + 3 < C2_H) dst[ox + 3] = fmaxf(HI(accB[oc]) + bias, 0.f);
        }
    }
}

// ---------------------------------------------------------------------------
// FC1 split-K GEMM (M=256, N=120, K=55815), maxpool-2 fused into the A load.
// BM=64, BN=120, BK=32, 240 threads, thread tile 4x8. B tile stored PACKED
// (f32x2-duplicated) so the inner loop has zero BPACK movs.
// Grid (4, 148) = 592 blocks = exactly 4/SM. Deterministic partials.
// ---------------------------------------------------------------------------
__global__ __launch_bounds__(240) void fc1_kernel(const float* __restrict__ fc1_w) {
    const int m0 = blockIdx.x * 64;
    const int k0 = blockIdx.y * KCHUNK;
    const int kend = min(k0 + KCHUNK, K_FC1);

    __shared__ float As[32][68];     // [kk][row], 16B-aligned rows
    __shared__ ull Bsp[32][120];     // packed-duplicated B

    const int tid = threadIdx.x;
    const int mg = tid & 15;         // 16 row-groups of 4
    const int ng = tid >> 4;         // 15 col-groups of 8

    ull acc2[2][8];
#pragma unroll
    for (int i = 0; i < 2; i++)
#pragma unroll
        for (int j = 0; j < 8; j++) acc2[i][j] = 0ULL;

    for (int kb = k0; kb < kend; kb += 32) {
        // A tile: 64 rows x 32 k, maxpool of g_conv2 on the fly
#pragma unroll
        for (int i = 0; i < 9; i++) {
            int idx = tid + i * 240;
            if (idx < 2048) {
                int r = idx >> 5, kk = idx & 31;
                int k = kb + kk;
                float v = 0.f;
                if (k < kend) {
                    int c = k / 3721;
                    int rem = k - c * 3721;
                    int y = rem / 61;
                    int xx = rem - y * 61;
                    const float* p = g_conv2 +
                        ((size_t)((m0 + r) * C2_OUT + c) * C2_H + y) * C2_H + xx;
                    v = fmaxf(fmaxf(p[0], p[1]), fmaxf(p[C2_H], p[C2_H + 1]));
                }
                As[kk][r] = v;
            }
        }
        // B tile: 120 n x 32 k, packed-duplicated
#pragma unroll
        for (int i = 0; i < 16; i++) {
            int idx = tid + i * 240;
            int n = idx >> 5, kk = idx & 31;
            int k = kb + kk;
            float v = (k < kend) ? fc1_w[(size_t)n * K_FC1 + k] : 0.f;
            ull p; BPACK(p, v);
            Bsp[kk][n] = p;
        }
        __syncthreads();

#pragma unroll
        for (int kk = 0; kk < 32; kk++) {
            float4 a = *(const float4*)&As[kk][mg * 4];
            ull a01, a23;
            PACK2(a01, a.x, a.y);
            PACK2(a23, a.z, a.w);
            const ull* bp = &Bsp[kk][ng * 8];
#pragma unroll
            for (int j = 0; j < 8; j++) {
                ull bb = bp[j];
                FMA2(acc2[0][j], a01, bb);
                FMA2(acc2[1][j], a23, bb);
            }
        }
        __syncthreads();
    }

    float* dst = g_fc1_part[blockIdx.y];
#pragma unroll
    for (int i = 0; i < 2; i++) {
        int row = m0 + mg * 4 + 2 * i;
#pragma unroll
        for (int j = 0; j < 8; j++) {
            dst[row * N_FC1 + ng * 8 + j] = LO(acc2[i][j]);
            dst[(row + 1) * N_FC1 + ng * 8 + j] = HI(acc2[i][j]);
        }
    }
}

// ---------------------------------------------------------------------------
// Head: reduce FC1 partials + bias + ReLU, FC2+ReLU, FC3, quantum statevector
// sim (4 qubits), softmax. One block per batch sample.
// ---------------------------------------------------------------------------
__global__ void head_kernel(const float* __restrict__ fc1_b,
                            const float* __restrict__ fc2_w,
                            const float* __restrict__ fc2_b,
                            const float* __restrict__ fc3_w,
                            const float* __restrict__ fc3_b,
                            const float* __restrict__ qw,
                            float* __restrict__ out) {
    const int b = blockIdx.x;
    __shared__ float h1[N_FC1];
    __shared__ float h2[N_FC2];
    __shared__ float ang[4];
    const int t = threadIdx.x;

    if (t < N_FC1) {
        float s = fc1_b[t];
#pragma unroll 4
        for (int j = 0; j < KSPLIT; j++) s += g_fc1_part[j][b * N_FC1 + t];
        h1[t] = fmaxf(s, 0.f);
    }
    __syncthreads();

    if (t < N_FC2) {
        float a = fc2_b[t];
#pragma unroll 8
        for (int k = 0; k < N_FC1; k++) a += h1[k] * fc2_w[t * N_FC1 + k];
        h2[t] = fmaxf(a, 0.f);
    }
    __syncthreads();

    if (t < 4) {
        float a = fc3_b[t];
#pragma unroll 4
        for (int k = 0; k < N_FC2; k++) a += h2[k] * fc3_w[t * N_FC2 + k];
        ang[t] = a;
    }
    __syncthreads();

    if (t == 0) {
        float sr[16], si[16];
#pragma unroll
        for (int i = 0; i < 16; i++) { sr[i] = 0.f; si[i] = 0.f; }
        sr[0] = 1.f;

#pragma unroll
        for (int q = 0; q < 4; q++) {
            float th = ang[q] * 0.5f;
            float c = cosf(th), s = sinf(th);
            const int bit = 1 << (3 - q);
#pragma unroll
            for (int i0 = 0; i0 < 16; i0++) {
                if (i0 & bit) continue;
                int i1 = i0 | bit;
                float a0r = sr[i0], a0i = si[i0], a1r = sr[i1], a1i = si[i1];
                sr[i0] = c * a0r + s * a1i;  si[i0] = c * a0i - s * a1r;
                sr[i1] = c * a1r + s * a0i;  si[i1] = c * a1i - s * a0r;
            }
        }
        int w = 0;
#pragma unroll
        for (int d = 0; d < 2; d++) {
#pragma unroll
            for (int q = 0; q < 4; q++) {
                float th = qw[w++] * 0.5f;
                float c = cosf(th), s = sinf(th);
                const int bit = 1 << (3 - q);
#pragma unroll
                for (int i0 = 0; i0 < 16; i0++) {
                    if (i0 & bit) continue;
                    int i1 = i0 | bit;
                    float a0r = sr[i0], a0i = si[i0], a1r = sr[i1], a1i = si[i1];
                    sr[i0] = c * a0r - s * a1r;  si[i0] = c * a0i - s * a1i;
                    sr[i1] = s * a0r + c * a1r;  si[i1] = s * a0i + c * a1i;
                }
            }
#pragma unroll
            for (int q = 0; q < 3; q++) {
                const int m1 = 1 << (3 - q), m2 = 1 << (2 - q);
#pragma unroll
                for (int i = 0; i < 16; i++)
                    if ((i & m1) && (i & m2)) { sr[i] = -sr[i]; si[i] = -si[i]; }
            }
        }
        float l0 = 0.f, l1 = 0.f;
#pragma unroll
        for (int i = 0; i < 16; i++) {
            float p = sr[i] * sr[i] + si[i] * si[i];
            l0 += (i & 8) ? -p : p;
            l1 += (i & 4) ? -p : p;
        }
        float m = fmaxf(l0, l1);
        float e0 = __expf(l0 - m), e1 = __expf(l1 - m);
        float inv = 1.f / (e0 + e1);
        out[b * 2 + 0] = e0 * inv;
        out[b * 2 + 1] = e1 * inv;
    }
}

// ---------------------------------------------------------------------------
extern "C" void kernel_launch(void* const* d_in, const int* in_sizes, int n_in,
                              void* d_out, int out_size) {
    const float* x     = (const float*)d_in[0];
    const float* w1    = (const float*)d_in[1];
    const float* b1    = (const float*)d_in[2];
    const float* w2    = (const float*)d_in[3];
    const float* b2    = (const float*)d_in[4];
    const float* fc1_w = (const float*)d_in[5];
    const float* fc1_b = (const float*)d_in[6];
    const float* fc2_w = (const float*)d_in[7];
    const float* fc2_b = (const float*)d_in[8];
    const float* fc3_w = (const float*)d_in[9];
    const float* fc3_b = (const float*)d_in[10];
    const float* qw    = (const float*)d_in[11];
    float* out = (float*)d_out;

    cudaFuncSetAttribute(conv1_kernel, cudaFuncAttributeMaxDynamicSharedMemorySize, C1_SMEM_BYTES);
    cudaFuncSetAttribute(conv2_kernel, cudaFuncAttributeMaxDynamicSharedMemorySize, C2_SMEM_BYTES);

    conv1_kernel<<<dim3(4, 4, BATCH), 256, C1_SMEM_BYTES>>>(x, w1, b1);
    conv2_kernel<<<dim3(2, 2, BATCH), 256, C2_SMEM_BYTES>>>(w2, b2);
    fc1_kernel<<<dim3(4, KSPLIT), 240>>>(fc1_w);
    head_kernel<<<BATCH, 128>>>(fc1_b, fc2_w, fc2_b, fc3_w, fc3_b, qw, out);
}

// round 5
// speedup vs baseline: 1.0484x; 1.0484x over previous
#include <cuda_runtime.h>
#include <cuda_fp16.h>
#include <math.h>

#define BATCH 256
#define C1_IN 3
#define C1_OUT 6
#define H_IN 250
#define C1_H 124          // conv1 out H/W
#define P1_H 123          // pool1 out H/W
#define C2_OUT 15
#define C2_H 62           // conv2 out H/W
#define P2_H 61           // pool2 out H/W
#define K_FC1 55815       // 15*61*61
#define N_FC1 120
#define N_FC2 84
#define KSPLIT 74
#define KCHUNK 755        // ceil(55815/74)

typedef unsigned long long ull;

// Scratch (static device globals — allocation-free). fp16 intermediates:
// halves DRAM traffic on the two big tensors (DRAM-bound pipeline).
__device__ __half g_conv1[(size_t)BATCH * C1_OUT * C1_H * C1_H];   // 47.2 MB
__device__ __half g_conv2[(size_t)BATCH * C2_OUT * C2_H * C2_H];   // 29.5 MB
__device__ float  g_fc1_part[KSPLIT][BATCH * N_FC1];               // 9.1 MB

// packed f32x2 helpers
#define BPACK(dst, f) asm("mov.b64 %0, {%1, %1};" : "=l"(dst) : "r"(__float_as_uint(f)))
#define PACK2(dst, lo, hi) asm("mov.b64 %0, {%1, %2};" : "=l"(dst) : "r"(__float_as_uint(lo)), "r"(__float_as_uint(hi)))
#define FMA2(acc, a, b) asm("fma.rn.f32x2 %0, %1, %2, %0;" : "+l"(acc) : "l"(a), "l"(b))
#define LO(v) __uint_as_float((unsigned)((v) & 0xffffffffULL))
#define HI(v) __uint_as_float((unsigned)((v) >> 32))

// ---------------------------------------------------------------------------
// conv1: 3->6, 5x5, stride 2, pad 1, + ReLU.  One block = 32x32 output tile,
// all 6 oc in registers (2x2 px * 6 oc = 24 accumulators). fp16 store.
// Dynamic smem: S[3][67][67] + W[450] + Bias[6]
// ---------------------------------------------------------------------------
#define C1_SW 67
#define C1_S_ELEMS (3 * C1_SW * C1_SW)
#define C1_SMEM_BYTES ((C1_S_ELEMS + 450 + 6 + 8) * 4)

__global__ __launch_bounds__(256) void conv1_kernel(const float* __restrict__ x,
                                                    const float* __restrict__ w1,
                                                    const float* __restrict__ b1) {
    extern __shared__ float sm1[];
    float* S = sm1;                      // [3][67][67]
    float* W = sm1 + C1_S_ELEMS;         // [6][3][5][5]
    float* Bias = W + 450;

    const int b = blockIdx.z;
    const int ox0 = blockIdx.x * 32, oy0 = blockIdx.y * 32;
    const int tx = threadIdx.x, ty = threadIdx.y;
    const int tid = ty * 16 + tx;

    for (int i = tid; i < 450; i += 256) W[i] = w1[i];
    if (tid < 6) Bias[tid] = b1[tid];

    const int iy0 = oy0 * 2 - 1, ix0 = ox0 * 2 - 1;
    const float* xb = x + (size_t)b * C1_IN * H_IN * H_IN;

    for (int idx = tid; idx < C1_S_ELEMS; idx += 256) {
        int c = idx / (C1_SW * C1_SW), r = idx % (C1_SW * C1_SW);
        int y = r / C1_SW, xx = r % C1_SW;
        int iy = iy0 + y, ix = ix0 + xx;
        float v = 0.f;
        if (iy >= 0 && iy < H_IN && ix >= 0 && ix < H_IN)
            v = xb[(c * H_IN + iy) * H_IN + ix];
        S[idx] = v;
    }
    __syncthreads();

    float acc[4][6];
#pragma unroll
    for (int p = 0; p < 4; p++)
#pragma unroll
        for (int oc = 0; oc < 6; oc++) acc[p][oc] = 0.f;

#pragma unroll
    for (int c = 0; c < 3; c++) {
        const float* Sc = S + c * C1_SW * C1_SW;
#pragma unroll
        for (int ky = 0; ky < 5; ky++) {
            const float* r0 = Sc + (ty * 2 + ky) * C1_SW;
            const float* r1 = Sc + (ty * 2 + 32 + ky) * C1_SW;
#pragma unroll
            for (int kx = 0; kx < 5; kx++) {
                float s0 = r0[tx * 2 + kx];
                float s1 = r0[tx * 2 + 32 + kx];
                float s2 = r1[tx * 2 + kx];
                float s3 = r1[tx * 2 + 32 + kx];
#pragma unroll
                for (int oc = 0; oc < 6; oc++) {
                    float w = W[((oc * 3 + c) * 5 + ky) * 5 + kx];
                    acc[0][oc] += s0 * w;
                    acc[1][oc] += s1 * w;
                    acc[2][oc] += s2 * w;
                    acc[3][oc] += s3 * w;
                }
            }
        }
    }

#pragma unroll
    for (int p = 0; p < 4; p++) {
        int ox = ox0 + tx + (p & 1) * 16;
        int oy = oy0 + ty + (p >> 1) * 16;
        if (ox < C1_H && oy < C1_H) {
#pragma unroll
            for (int oc = 0; oc < 6; oc++)
                g_conv1[((size_t)(b * C1_OUT + oc) * C1_H + oy) * C1_H + ox] =
                    __float2half(fmaxf(acc[p][oc] + Bias[oc], 0.f));
        }
    }
}

// ---------------------------------------------------------------------------
// conv2: maxpool(2,s1) fused into smem load (fp16 source); 6->15, 3x3,
// stride 2, pad 1, ReLU. One block = 32x32 tile, all 15 oc. fp16 store.
// Dynamic smem: P[6][65][65] + W[810] + Bias[15]
// ---------------------------------------------------------------------------
#define C2_SW 65
#define C2_P_ELEMS (6 * C2_SW * C2_SW)
#define C2_SMEM_BYTES ((C2_P_ELEMS + 810 + 15 + 8) * 4)

__global__ __launch_bounds__(256) void conv2_kernel(const float* __restrict__ w2,
                                                    const float* __restrict__ b2) {
    extern __shared__ float sm2[];
    float* P = sm2;                      // [6][65][65]
    float* W = sm2 + C2_P_ELEMS;         // [15][6][3][3]
    float* Bias = W + 810;

    const int b = blockIdx.z;
    const int ox0 = blockIdx.x * 32, oy0 = blockIdx.y * 32;
    const int tx = threadIdx.x, ty = threadIdx.y;
    const int tid = ty * 16 + tx;

    for (int i = tid; i < 810; i += 256) W[i] = w2[i];
    if (tid < 15) Bias[tid] = b2[tid];

    const int py0 = oy0 * 2 - 1, px0 = ox0 * 2 - 1;
    const __half* cb = g_conv1 + (size_t)b * C1_OUT * C1_H * C1_H;

    for (int idx = tid; idx < C2_P_ELEMS; idx += 256) {
        int c = idx / (C2_SW * C2_SW), r = idx % (C2_SW * C2_SW);
        int y = r / C2_SW, xx = r % C2_SW;
        int py = py0 + y, px = px0 + xx;
        float v = 0.f;
        if (py >= 0 && py < P1_H && px >= 0 && px < P1_H) {
            const __half* p = cb + (c * C1_H + py) * C1_H + px;
            float v00 = __half2float(p[0]),     v01 = __half2float(p[1]);
            float v10 = __half2float(p[C1_H]),  v11 = __half2float(p[C1_H + 1]);
            v = fmaxf(fmaxf(v00, v01), fmaxf(v10, v11));
        }
        P[idx] = v;
    }
    __syncthreads();

    float acc[4][15];
#pragma unroll
    for (int p = 0; p < 4; p++)
#pragma unroll
        for (int oc = 0; oc < 15; oc++) acc[p][oc] = 0.f;

#pragma unroll
    for (int c = 0; c < 6; c++) {
        const float* Pc = P + c * C2_SW * C2_SW;
#pragma unroll
        for (int ky = 0; ky < 3; ky++) {
            const float* r0 = Pc + (ty * 2 + ky) * C2_SW;
            const float* r1 = Pc + (ty * 2 + 32 + ky) * C2_SW;
#pragma unroll
            for (int kx = 0; kx < 3; kx++) {
                float s0 = r0[tx * 2 + kx];
                float s1 = r0[tx * 2 + 32 + kx];
                float s2 = r1[tx * 2 + kx];
                float s3 = r1[tx * 2 + 32 + kx];
#pragma unroll
                for (int oc = 0; oc < 15; oc++) {
                    float w = W[((oc * 6 + c) * 3 + ky) * 3 + kx];
                    acc[0][oc] += s0 * w;
                    acc[1][oc] += s1 * w;
                    acc[2][oc] += s2 * w;
                    acc[3][oc] += s3 * w;
                }
            }
        }
    }

#pragma unroll
    for (int p = 0; p < 4; p++) {
        int ox = ox0 + tx + (p & 1) * 16;
        int oy = oy0 + ty + (p >> 1) * 16;
        if (ox < C2_H && oy < C2_H) {
#pragma unroll
            for (int oc = 0; oc < 15; oc++)
                g_conv2[((size_t)(b * C2_OUT + oc) * C2_H + oy) * C2_H + ox] =
                    __float2half(fmaxf(acc[p][oc] + Bias[oc], 0.f));
        }
    }
}

// ---------------------------------------------------------------------------
// FC1 split-K GEMM (M=256, N=120, K=55815), maxpool-2 fused into the A load
// (fp16 source). BM=64, BN=120, BK=32, 240 threads, thread tile 4x8,
// B tile pre-packed f32x2. Grid (4, 74) = 296 blocks. Deterministic partials.
// ---------------------------------------------------------------------------
__global__ __launch_bounds__(240) void fc1_kernel(const float* __restrict__ fc1_w) {
    const int m0 = blockIdx.x * 64;
    const int k0 = blockIdx.y * KCHUNK;
    const int kend = min(k0 + KCHUNK, K_FC1);

    __shared__ float As[32][68];     // [kk][row], 16B-aligned rows
    __shared__ ull Bsp[32][120];     // packed-duplicated B

    const int tid = threadIdx.x;
    const int mg = tid & 15;         // 16 row-groups of 4
    const int ng = tid >> 4;         // 15 col-groups of 8

    ull acc2[2][8];
#pragma unroll
    for (int i = 0; i < 2; i++)
#pragma unroll
        for (int j = 0; j < 8; j++) acc2[i][j] = 0ULL;

    for (int kb = k0; kb < kend; kb += 32) {
        // A tile: 64 rows x 32 k, maxpool of fp16 g_conv2 on the fly
#pragma unroll
        for (int i = 0; i < 9; i++) {
            int idx = tid + i * 240;
            if (idx < 2048) {
                int r = idx >> 5, kk = idx & 31;
                int k = kb + kk;
                float v = 0.f;
                if (k < kend) {
                    int c = k / 3721;
                    int rem = k - c * 3721;
                    int y = rem / 61;
                    int xx = rem - y * 61;
                    const __half* p = g_conv2 +
                        ((size_t)((m0 + r) * C2_OUT + c) * C2_H + y) * C2_H + xx;
                    float v00 = __half2float(p[0]),     v01 = __half2float(p[1]);
                    float v10 = __half2float(p[C2_H]),  v11 = __half2float(p[C2_H + 1]);
                    v = fmaxf(fmaxf(v00, v01), fmaxf(v10, v11));
                }
                As[kk][r] = v;
            }
        }
        // B tile: 120 n x 32 k, packed-duplicated (fc1_w [120, 55815] row-major)
#pragma unroll
        for (int i = 0; i < 16; i++) {
            int idx = tid + i * 240;
            int n = idx >> 5, kk = idx & 31;
            int k = kb + kk;
            float v = (k < kend) ? fc1_w[(size_t)n * K_FC1 + k] : 0.f;
            ull p; BPACK(p, v);
            Bsp[kk][n] = p;
        }
        __syncthreads();

#pragma unroll
        for (int kk = 0; kk < 32; kk++) {
            float4 a = *(const float4*)&As[kk][mg * 4];
            ull a01, a23;
            PACK2(a01, a.x, a.y);
            PACK2(a23, a.z, a.w);
            const ull* bp = &Bsp[kk][ng * 8];
#pragma unroll
            for (int j = 0; j < 8; j++) {
                ull bb = bp[j];
                FMA2(acc2[0][j], a01, bb);
                FMA2(acc2[1][j], a23, bb);
            }
        }
        __syncthreads();
    }

    float* dst = g_fc1_part[blockIdx.y];
#pragma unroll
    for (int i = 0; i < 2; i++) {
        int row = m0 + mg * 4 + 2 * i;
#pragma unroll
        for (int j = 0; j < 8; j++) {
            dst[row * N_FC1 + ng * 8 + j] = LO(acc2[i][j]);
            dst[(row + 1) * N_FC1 + ng * 8 + j] = HI(acc2[i][j]);
        }
    }
}

// ---------------------------------------------------------------------------
// Head: reduce FC1 partials + bias + ReLU, FC2+ReLU, FC3, quantum statevector
// sim (4 qubits), softmax. One block per batch sample.
// ---------------------------------------------------------------------------
__global__ void head_kernel(const float* __restrict__ fc1_b,
                            const float* __restrict__ fc2_w,
                            const float* __restrict__ fc2_b,
                            const float* __restrict__ fc3_w,
                            const float* __restrict__ fc3_b,
                            const float* __restrict__ qw,
                            float* __restrict__ out) {
    const int b = blockIdx.x;
    __shared__ float h1[N_FC1];
    __shared__ float h2[N_FC2];
    __shared__ float ang[4];
    const int t = threadIdx.x;

    if (t < N_FC1) {
        float s = fc1_b[t];
#pragma unroll 16
        for (int j = 0; j < KSPLIT; j++) s += g_fc1_part[j][b * N_FC1 + t];
        h1[t] = fmaxf(s, 0.f);
    }
    __syncthreads();

    if (t < N_FC2) {
        float a = fc2_b[t];
#pragma unroll 8
        for (int k = 0; k < N_FC1; k++) a += h1[k] * fc2_w[t * N_FC1 + k];
        h2[t] = fmaxf(a, 0.f);
    }
    __syncthreads();

    if (t < 4) {
        float a = fc3_b[t];
#pragma unroll 4
        for (int k = 0; k < N_FC2; k++) a += h2[k] * fc3_w[t * N_FC2 + k];
        ang[t] = a;
    }
    __syncthreads();

    if (t == 0) {
        float sr[16], si[16];
#pragma unroll
        for (int i = 0; i < 16; i++) { sr[i] = 0.f; si[i] = 0.f; }
        sr[0] = 1.f;

#pragma unroll
        for (int q = 0; q < 4; q++) {
            float th = ang[q] * 0.5f;
            float c = cosf(th), s = sinf(th);
            const int bit = 1 << (3 - q);
#pragma unroll
            for (int i0 = 0; i0 < 16; i0++) {
                if (i0 & bit) continue;
                int i1 = i0 | bit;
                float a0r = sr[i0], a0i = si[i0], a1r = sr[i1], a1i = si[i1];
                sr[i0] = c * a0r + s * a1i;  si[i0] = c * a0i - s * a1r;
                sr[i1] = c * a1r + s * a0i;  si[i1] = c * a1i - s * a0r;
            }
        }
        int w = 0;
#pragma unroll
        for (int d = 0; d < 2; d++) {
#pragma unroll
            for (int q = 0; q < 4; q++) {
                float th = qw[w++] * 0.5f;
                float c = cosf(th), s = sinf(th);
                const int bit = 1 << (3 - q);
#pragma unroll
                for (int i0 = 0; i0 < 16; i0++) {
                    if (i0 & bit) continue;
                    int i1 = i0 | bit;
                    float a0r = sr[i0], a0i = si[i0], a1r = sr[i1], a1i = si[i1];
                    sr[i0] = c * a0r - s * a1r;  si[i0] = c * a0i - s * a1i;
                    sr[i1] = s * a0r + c * a1r;  si[i1] = s * a0i + c * a1i;
                }
            }
#pragma unroll
            for (int q = 0; q < 3; q++) {
                const int m1 = 1 << (3 - q), m2 = 1 << (2 - q);
#pragma unroll
                for (int i = 0; i < 16; i++)
                    if ((i & m1) && (i & m2)) { sr[i] = -sr[i]; si[i] = -si[i]; }
            }
        }
        float l0 = 0.f, l1 = 0.f;
#pragma unroll
        for (int i = 0; i < 16; i++) {
            float p = sr[i] * sr[i] + si[i] * si[i];
            l0 += (i & 8) ? -p : p;
            l1 += (i & 4) ? -p : p;
        }
        float m = fmaxf(l0, l1);
        float e0 = __expf(l0 - m), e1 = __expf(l1 - m);
        float inv = 1.f / (e0 + e1);
        out[b * 2 + 0] = e0 * inv;
        out[b * 2 + 1] = e1 * inv;
    }
}

// ---------------------------------------------------------------------------
extern "C" void kernel_launch(void* const* d_in, const int* in_sizes, int n_in,
                              void* d_out, int out_size) {
    const float* x     = (const float*)d_in[0];
    const float* w1    = (const float*)d_in[1];
    const float* b1    = (const float*)d_in[2];
    const float* w2    = (const float*)d_in[3];
    const float* b2    = (const float*)d_in[4];
    const float* fc1_w = (const float*)d_in[5];
    const float* fc1_b = (const float*)d_in[6];
    const float* fc2_w = (const float*)d_in[7];
    const float* fc2_b = (const float*)d_in[8];
    const float* fc3_w = (const float*)d_in[9];
    const float* fc3_b = (const float*)d_in[10];
    const float* qw    = (const float*)d_in[11];
    float* out = (float*)d_out;

    cudaFuncSetAttribute(conv1_kernel, cudaFuncAttributeMaxDynamicSharedMemorySize, C1_SMEM_BYTES);
    cudaFuncSetAttribute(conv2_kernel, cudaFuncAttributeMaxDynamicSharedMemorySize, C2_SMEM_BYTES);

    dim3 blk(16, 16);
    conv1_kernel<<<dim3(4, 4, BATCH), blk, C1_SMEM_BYTES>>>(x, w1, b1);
    conv2_kernel<<<dim3(2, 2, BATCH), blk, C2_SMEM_BYTES>>>(w2, b2);
    fc1_kernel<<<dim3(4, KSPLIT), 240>>>(fc1_w);
    head_kernel<<<BATCH, 128>>>(fc1_b, fc2_w, fc2_b, fc3_w, fc3_b, qw, out);
}

// round 6
// speedup vs baseline: 1.2572x; 1.1991x over previous
#include <cuda_runtime.h>
#include <cuda_fp16.h>
#include <math.h>

#define BATCH 256
#define C1_IN 3
#define C1_OUT 6
#define H_IN 250
#define C1_H 124          // conv1 out H/W
#define P1_H 123          // pool1 out H/W
#define C2_OUT 15
#define C2_H 62           // conv2 out H/W
#define P2_H 61           // pool2 out H/W
#define K_FC1 55815       // 15*61*61
#define N_FC1 120
#define N_FC2 84
#define KSPLIT 74
#define KCHUNK 755        // ceil(55815/74)

typedef unsigned long long ull;

// Scratch (static device globals — allocation-free)
__device__ __half g_conv1[(size_t)BATCH * C1_OUT * C1_H * C1_H];   // 47.2 MB
__device__ __half g_conv2[(size_t)BATCH * C2_OUT * C2_H * C2_H];   // 29.5 MB
__device__ float  g_fc1_part[KSPLIT][BATCH * N_FC1];               // 9.1 MB

// ---------------------------------------------------------------------------
// conv1: 3->6, 5x5, stride 2, pad 1, + ReLU. (identical to 576us baseline)
// ---------------------------------------------------------------------------
#define C1_SW 67
#define C1_S_ELEMS (3 * C1_SW * C1_SW)
#define C1_SMEM_BYTES ((C1_S_ELEMS + 450 + 6 + 8) * 4)

__global__ __launch_bounds__(256) void conv1_kernel(const float* __restrict__ x,
                                                    const float* __restrict__ w1,
                                                    const float* __restrict__ b1) {
    extern __shared__ float sm1[];
    float* S = sm1;                      // [3][67][67]
    float* W = sm1 + C1_S_ELEMS;         // [6][3][5][5]
    float* Bias = W + 450;

    const int b = blockIdx.z;
    const int ox0 = blockIdx.x * 32, oy0 = blockIdx.y * 32;
    const int tx = threadIdx.x, ty = threadIdx.y;
    const int tid = ty * 16 + tx;

    for (int i = tid; i < 450; i += 256) W[i] = w1[i];
    if (tid < 6) Bias[tid] = b1[tid];

    const int iy0 = oy0 * 2 - 1, ix0 = ox0 * 2 - 1;
    const float* xb = x + (size_t)b * C1_IN * H_IN * H_IN;

    for (int idx = tid; idx < C1_S_ELEMS; idx += 256) {
        int c = idx / (C1_SW * C1_SW), r = idx % (C1_SW * C1_SW);
        int y = r / C1_SW, xx = r % C1_SW;
        int iy = iy0 + y, ix = ix0 + xx;
        float v = 0.f;
        if (iy >= 0 && iy < H_IN && ix >= 0 && ix < H_IN)
            v = xb[(c * H_IN + iy) * H_IN + ix];
        S[idx] = v;
    }
    __syncthreads();

    float acc[4][6];
#pragma unroll
    for (int p = 0; p < 4; p++)
#pragma unroll
        for (int oc = 0; oc < 6; oc++) acc[p][oc] = 0.f;

#pragma unroll
    for (int c = 0; c < 3; c++) {
        const float* Sc = S + c * C1_SW * C1_SW;
#pragma unroll
        for (int ky = 0; ky < 5; ky++) {
            const float* r0 = Sc + (ty * 2 + ky) * C1_SW;
            const float* r1 = Sc + (ty * 2 + 32 + ky) * C1_SW;
#pragma unroll
            for (int kx = 0; kx < 5; kx++) {
                float s0 = r0[tx * 2 + kx];
                float s1 = r0[tx * 2 + 32 + kx];
                float s2 = r1[tx * 2 + kx];
                float s3 = r1[tx * 2 + 32 + kx];
#pragma unroll
                for (int oc = 0; oc < 6; oc++) {
                    float w = W[((oc * 3 + c) * 5 + ky) * 5 + kx];
                    acc[0][oc] += s0 * w;
                    acc[1][oc] += s1 * w;
                    acc[2][oc] += s2 * w;
                    acc[3][oc] += s3 * w;
                }
            }
        }
    }

#pragma unroll
    for (int p = 0; p < 4; p++) {
        int ox = ox0 + tx + (p & 1) * 16;
        int oy = oy0 + ty + (p >> 1) * 16;
        if (ox < C1_H && oy < C1_H) {
#pragma unroll
            for (int oc = 0; oc < 6; oc++)
                g_conv1[((size_t)(b * C1_OUT + oc) * C1_H + oy) * C1_H + ox] =
                    __float2half(fmaxf(acc[p][oc] + Bias[oc], 0.f));
        }
    }
}

// ---------------------------------------------------------------------------
// conv2: maxpool(2,s1) fused; 6->15, 3x3, s2, pad 1, ReLU. (identical)
// ---------------------------------------------------------------------------
#define C2_SW 65
#define C2_P_ELEMS (6 * C2_SW * C2_SW)
#define C2_SMEM_BYTES ((C2_P_ELEMS + 810 + 15 + 8) * 4)

__global__ __launch_bounds__(256) void conv2_kernel(const float* __restrict__ w2,
                                                    const float* __restrict__ b2) {
    extern __shared__ float sm2[];
    float* P = sm2;                      // [6][65][65]
    float* W = sm2 + C2_P_ELEMS;         // [15][6][3][3]
    float* Bias = W + 810;

    const int b = blockIdx.z;
    const int ox0 = blockIdx.x * 32, oy0 = blockIdx.y * 32;
    const int tx = threadIdx.x, ty = threadIdx.y;
    const int tid = ty * 16 + tx;

    for (int i = tid; i < 810; i += 256) W[i] = w2[i];
    if (tid < 15) Bias[tid] = b2[tid];

    const int py0 = oy0 * 2 - 1, px0 = ox0 * 2 - 1;
    const __half* cb = g_conv1 + (size_t)b * C1_OUT * C1_H * C1_H;

    for (int idx = tid; idx < C2_P_ELEMS; idx += 256) {
        int c = idx / (C2_SW * C2_SW), r = idx % (C2_SW * C2_SW);
        int y = r / C2_SW, xx = r % C2_SW;
        int py = py0 + y, px = px0 + xx;
        float v = 0.f;
        if (py >= 0 && py < P1_H && px >= 0 && px < P1_H) {
            const __half* p = cb + (c * C1_H + py) * C1_H + px;
            float v00 = __half2float(p[0]),     v01 = __half2float(p[1]);
            float v10 = __half2float(p[C1_H]),  v11 = __half2float(p[C1_H + 1]);
            v = fmaxf(fmaxf(v00, v01), fmaxf(v10, v11));
        }
        P[idx] = v;
    }
    __syncthreads();

    float acc[4][15];
#pragma unroll
    for (int p = 0; p < 4; p++)
#pragma unroll
        for (int oc = 0; oc < 15; oc++) acc[p][oc] = 0.f;

#pragma unroll
    for (int c = 0; c < 6; c++) {
        const float* Pc = P + c * C2_SW * C2_SW;
#pragma unroll
        for (int ky = 0; ky < 3; ky++) {
            const float* r0 = Pc + (ty * 2 + ky) * C2_SW;
            const float* r1 = Pc + (ty * 2 + 32 + ky) * C2_SW;
#pragma unroll
            for (int kx = 0; kx < 3; kx++) {
                float s0 = r0[tx * 2 + kx];
                float s1 = r0[tx * 2 + 32 + kx];
                float s2 = r1[tx * 2 + kx];
                float s3 = r1[tx * 2 + 32 + kx];
#pragma unroll
                for (int oc = 0; oc < 15; oc++) {
                    float w = W[((oc * 6 + c) * 3 + ky) * 3 + kx];
                    acc[0][oc] += s0 * w;
                    acc[1][oc] += s1 * w;
                    acc[2][oc] += s2 * w;
                    acc[3][oc] += s3 * w;
                }
            }
        }
    }

#pragma unroll
    for (int p = 0; p < 4; p++) {
        int ox = ox0 + tx + (p & 1) * 16;
        int oy = oy0 + ty + (p >> 1) * 16;
        if (ox < C2_H && oy < C2_H) {
#pragma unroll
            for (int oc = 0; oc < 15; oc++)
                g_conv2[((size_t)(b * C2_OUT + oc) * C2_H + oy) * C2_H + ox] =
                    __float2half(fmaxf(acc[p][oc] + Bias[oc], 0.f));
        }
    }
}

// ---------------------------------------------------------------------------
// FC1 via tensor cores: mma.sync.m16n8k16 f16*f16 -> f32.
// Split-K: grid (2, 74) = 148 blocks = 1/SM. BM=128, BN=120 (15 n8 tiles),
// BK=16. 8 warps, each owns one m16 slab x all 15 n-tiles (60 f32 acc regs).
// A = maxpool(g_conv2) gathered to fp16 smem; B = fc1_w fp32 -> fp16 inline.
// Register-buffered prefetch overlaps DRAM latency with mma compute.
// ---------------------------------------------------------------------------
#define FC1_BM 128
#define FC1_BK 16

#define LDSM_X4(r0, r1, r2, r3, addr) \
    asm volatile("ldmatrix.sync.aligned.m8n8.x4.shared.b16 {%0,%1,%2,%3}, [%4];" \
        : "=r"(r0), "=r"(r1), "=r"(r2), "=r"(r3) : "r"(addr))

#define LDSM_X2_T(r0, r1, addr) \
    asm volatile("ldmatrix.sync.aligned.m8n8.x2.trans.shared.b16 {%0,%1}, [%2];" \
        : "=r"(r0), "=r"(r1) : "r"(addr))

#define MMA_16816(c, a0, a1, a2, a3, b0, b1) \
    asm volatile("mma.sync.aligned.m16n8k16.row.col.f32.f16.f16.f32 " \
        "{%0,%1,%2,%3}, {%4,%5,%6,%7}, {%8,%9}, {%0,%1,%2,%3};" \
        : "+f"(c[0]), "+f"(c[1]), "+f"(c[2]), "+f"(c[3]) \
        : "r"(a0), "r"(a1), "r"(a2), "r"(a3), "r"(b0), "r"(b1))

__global__ __launch_bounds__(256) void fc1_mma_kernel(const float* __restrict__ fc1_w) {
    __shared__ __half As[FC1_BM][24];    // row stride 48B -> ldmatrix conflict-free
    __shared__ __half Bs[FC1_BK][136];   // row stride 272B -> conflict-free

    const int tid = threadIdx.x;
    const int lane = tid & 31, w = tid >> 5;
    const int m0 = blockIdx.x * FC1_BM;
    const int k0 = blockIdx.y * KCHUNK;
    const int kend = min(k0 + KCHUNK, K_FC1);

    float acc[15][4];
#pragma unroll
    for (int nt = 0; nt < 15; nt++)
#pragma unroll
        for (int i = 0; i < 4; i++) acc[nt][i] = 0.f;

    const int arow = tid >> 1;           // 0..127 (A row this thread fills)
    const int akk = (tid & 1) * 8;       // k-offset 0 or 8
    const int mrow = m0 + arow;

    __half ra[8];
    float rb[8];

    // ---- register loaders (prefetch) ----
    auto loadA = [&](int kb) {
        int k = kb + akk;
        int c = k / 3721;
        int rem = k - c * 3721;
        int y = rem / 61;
        int xx = rem - y * 61;
#pragma unroll
        for (int i = 0; i < 8; i++) {
            float v = 0.f;
            if (k + i < kend) {
                const __half* p = g_conv2 +
                    ((size_t)(mrow * C2_OUT + c) * C2_H + y) * C2_H + xx;
                float v00 = __half2float(p[0]),     v01 = __half2float(p[1]);
                float v10 = __half2float(p[C2_H]),  v11 = __half2float(p[C2_H + 1]);
                v = fmaxf(fmaxf(v00, v01), fmaxf(v10, v11));
            }
            ra[i] = __float2half(v);
            if (++xx == 61) { xx = 0; if (++y == 61) { y = 0; ++c; } }
        }
    };
    auto loadB = [&](int kb) {
#pragma unroll
        for (int i = 0; i < 8; i++) {
            int idx = tid + i * 256;     // n-major, k-minor: coalesced on fc1_w
            rb[i] = 0.f;
            if (idx < 1920) {
                int n = idx >> 4;        // 0..119
                int kk = idx & 15;
                int k = kb + kk;
                if (k < kend) rb[i] = fc1_w[(size_t)n * K_FC1 + k];
            }
        }
    };
    auto stsAB = [&]() {
        uint4 av;
        __half2* ah = (__half2*)&av;
        ah[0] = __halves2half2(ra[0], ra[1]);
        ah[1] = __halves2half2(ra[2], ra[3]);
        ah[2] = __halves2half2(ra[4], ra[5]);
        ah[3] = __halves2half2(ra[6], ra[7]);
        *(uint4*)&As[arow][akk] = av;
#pragma unroll
        for (int i = 0; i < 8; i++) {
            int idx = tid + i * 256;
            if (idx < 1920) Bs[idx & 15][idx >> 4] = __float2half(rb[i]);
        }
    };

    // ldmatrix source addresses (fixed per thread)
    const unsigned aaddr = (unsigned)__cvta_generic_to_shared(
        &As[w * 16 + (lane & 15)][(lane >> 4) * 8]);
    const unsigned baddr0 = (unsigned)__cvta_generic_to_shared(
        &Bs[lane & 15][0]);

    loadA(k0);
    loadB(k0);

    for (int kb = k0; kb < kend; kb += FC1_BK) {
        stsAB();
        __syncthreads();
        if (kb + FC1_BK < kend) { loadA(kb + FC1_BK); loadB(kb + FC1_BK); }

        unsigned a0, a1, a2, a3;
        LDSM_X4(a0, a1, a2, a3, aaddr);
#pragma unroll
        for (int nt = 0; nt < 15; nt++) {
            unsigned b0, b1;
            LDSM_X2_T(b0, b1, baddr0 + nt * 16);
            MMA_16816(acc[nt], a0, a1, a2, a3, b0, b1);
        }
        __syncthreads();
    }

    // epilogue: C fragment m16n8 -> g_fc1_part (all n < 120 by construction)
    const int r0 = m0 + w * 16 + (lane >> 2);
    const int cb = (lane & 3) * 2;
    float* dst = g_fc1_part[blockIdx.y];
#pragma unroll
    for (int nt = 0; nt < 15; nt++) {
        int cc = nt * 8 + cb;
        dst[r0 * N_FC1 + cc]           = acc[nt][0];
        dst[r0 * N_FC1 + cc + 1]       = acc[nt][1];
        dst[(r0 + 8) * N_FC1 + cc]     = acc[nt][2];
        dst[(r0 + 8) * N_FC1 + cc + 1] = acc[nt][3];
    }
}

// ---------------------------------------------------------------------------
// Head: reduce FC1 partials + bias + ReLU, FC2+ReLU, FC3, quantum statevector
// sim (4 qubits), softmax. One block per batch sample. (identical)
// ---------------------------------------------------------------------------
__global__ void head_kernel(const float* __restrict__ fc1_b,
                            const float* __restrict__ fc2_w,
                            const float* __restrict__ fc2_b,
                            const float* __restrict__ fc3_w,
                            const float* __restrict__ fc3_b,
                            const float* __restrict__ qw,
                            float* __restrict__ out) {
    const int b = blockIdx.x;
    __shared__ float h1[N_FC1];
    __shared__ float h2[N_FC2];
    __shared__ float ang[4];
    const int t = threadIdx.x;

    if (t < N_FC1) {
        float s = fc1_b[t];
#pragma unroll 16
        for (int j = 0; j < KSPLIT; j++) s += g_fc1_part[j][b * N_FC1 + t];
        h1[t] = fmaxf(s, 0.f);
    }
    __syncthreads();

    if (t < N_FC2) {
        float a = fc2_b[t];
#pragma unroll 8
        for (int k = 0; k < N_FC1; k++) a += h1[k] * fc2_w[t * N_FC1 + k];
        h2[t] = fmaxf(a, 0.f);
    }
    __syncthreads();

    if (t < 4) {
        float a = fc3_b[t];
#pragma unroll 4
        for (int k = 0; k < N_FC2; k++) a += h2[k] * fc3_w[t * N_FC2 + k];
        ang[t] = a;
    }
    __syncthreads();

    if (t == 0) {
        float sr[16], si[16];
#pragma unroll
        for (int i = 0; i < 16; i++) { sr[i] = 0.f; si[i] = 0.f; }
        sr[0] = 1.f;

#pragma unroll
        for (int q = 0; q < 4; q++) {
            float th = ang[q] * 0.5f;
            float c = cosf(th), s = sinf(th);
            const int bit = 1 << (3 - q);
#pragma unroll
            for (int i0 = 0; i0 < 16; i0++) {
                if (i0 & bit) continue;
                int i1 = i0 | bit;
                float a0r = sr[i0], a0i = si[i0], a1r = sr[i1], a1i = si[i1];
                sr[i0] = c * a0r + s * a1i;  si[i0] = c * a0i - s * a1r;
                sr[i1] = c * a1r + s * a0i;  si[i1] = c * a1i - s * a0r;
            }
        }
        int w = 0;
#pragma unroll
        for (int d = 0; d < 2; d++) {
#pragma unroll
            for (int q = 0; q < 4; q++) {
                float th = qw[w++] * 0.5f;
                float c = cosf(th), s = sinf(th);
                const int bit = 1 << (3 - q);
#pragma unroll
                for (int i0 = 0; i0 < 16; i0++) {
                    if (i0 & bit) continue;
                    int i1 = i0 | bit;
                    float a0r = sr[i0], a0i = si[i0], a1r = sr[i1], a1i = si[i1];
                    sr[i0] = c * a0r - s * a1r;  si[i0] = c * a0i - s * a1i;
                    sr[i1] = s * a0r + c * a1r;  si[i1] = s * a0i + c * a1i;
                }
            }
#pragma unroll
            for (int q = 0; q < 3; q++) {
                const int m1 = 1 << (3 - q), m2 = 1 << (2 - q);
#pragma unroll
                for (int i = 0; i < 16; i++)
                    if ((i & m1) && (i & m2)) { sr[i] = -sr[i]; si[i] = -si[i]; }
            }
        }
        float l0 = 0.f, l1 = 0.f;
#pragma unroll
        for (int i = 0; i < 16; i++) {
            float p = sr[i] * sr[i] + si[i] * si[i];
            l0 += (i & 8) ? -p : p;
            l1 += (i & 4) ? -p : p;
        }
        float m = fmaxf(l0, l1);
        float e0 = __expf(l0 - m), e1 = __expf(l1 - m);
        float inv = 1.f / (e0 + e1);
        out[b * 2 + 0] = e0 * inv;
        out[b * 2 + 1] = e1 * inv;
    }
}

// ---------------------------------------------------------------------------
extern "C" void kernel_launch(void* const* d_in, const int* in_sizes, int n_in,
                              void* d_out, int out_size) {
    const float* x     = (const float*)d_in[0];
    const float* w1    = (const float*)d_in[1];
    const float* b1    = (const float*)d_in[2];
    const float* w2    = (const float*)d_in[3];
    const float* b2    = (const float*)d_in[4];
    const float* fc1_w = (const float*)d_in[5];
    const float* fc1_b = (const float*)d_in[6];
    const float* fc2_w = (const float*)d_in[7];
    const float* fc2_b = (const float*)d_in[8];
    const float* fc3_w = (const float*)d_in[9];
    const float* fc3_b = (const float*)d_in[10];
    const float* qw    = (const float*)d_in[11];
    float* out = (float*)d_out;

    cudaFuncSetAttribute(conv1_kernel, cudaFuncAttributeMaxDynamicSharedMemorySize, C1_SMEM_BYTES);
    cudaFuncSetAttribute(conv2_kernel, cudaFuncAttributeMaxDynamicSharedMemorySize, C2_SMEM_BYTES);

    dim3 blk(16, 16);
    conv1_kernel<<<dim3(4, 4, BATCH), blk, C1_SMEM_BYTES>>>(x, w1, b1);
    conv2_kernel<<<dim3(2, 2, BATCH), blk, C2_SMEM_BYTES>>>(w2, b2);
    fc1_mma_kernel<<<dim3(2, KSPLIT), 256>>>(fc1_w);
    head_kernel<<<BATCH, 128>>>(fc1_b, fc2_w, fc2_b, fc3_w, fc3_b, qw, out);
}

// round 8
// speedup vs baseline: 1.4673x; 1.1672x over previous
#include <cuda_runtime.h>
#include <cuda_fp16.h>
#include <math.h>

#define BATCH 256
#define C1_IN 3
#define C1_OUT 6
#define H_IN 250
#define C1_H 124          // conv1 out H/W
#define P1_H 123          // pool1 out H/W
#define C2_OUT 15
#define C2_H 62           // conv2 out H/W
#define P2_H 61           // pool2 out H/W
#define K_FC1 55815       // 15*61*61
#define N_FC1 120
#define N_FC2 84
#define KSPLIT 74
#define KCHUNK 755        // ceil(55815/74)

typedef unsigned long long ull;

// Scratch (static device globals — allocation-free)
__device__ __half g_conv1[(size_t)BATCH * C1_OUT * C1_H * C1_H];   // 47.2 MB
__device__ __half g_conv2[(size_t)BATCH * C2_OUT * C2_H * C2_H];   // 29.5 MB
__device__ float  g_fc1_part[KSPLIT][BATCH * N_FC1];               // 9.1 MB

// packed f32x2 helpers
#define BPACK(dst, f) asm("mov.b64 %0, {%1, %1};" : "=l"(dst) : "r"(__float_as_uint(f)))
#define PACK2(dst, lo, hi) asm("mov.b64 %0, {%1, %2};" : "=l"(dst) : "r"(__float_as_uint(lo)), "r"(__float_as_uint(hi)))
#define FMA2(acc, a, b) asm("fma.rn.f32x2 %0, %1, %2, %0;" : "+l"(acc) : "l"(a), "l"(b))
#define LO(v) __uint_as_float((unsigned)((v) & 0xffffffffULL))
#define HI(v) __uint_as_float((unsigned)((v) >> 32))

// ---------------------------------------------------------------------------
// conv1: 3->6, 5x5, stride 2, pad 1, + ReLU.
// OCCUPANCY-FIRST: tile 32x16, smem ~31.9KB -> 7 blocks/SM (56 warps).
// Thread = 2 x-split px * 6 oc. Weights pre-packed f32x2 in smem.
// NOTE: Wp placed at EVEN float offset (C1_W_OFF) for 8B alignment of LDS.64.
// ---------------------------------------------------------------------------
#define C1_PITCH 67
#define C1_ROWS 35
#define C1_S_ELEMS (3 * C1_ROWS * C1_PITCH)        // 7035 (odd!)
#define C1_W_OFF 7036                               // even -> 8B-aligned ull*
#define C1_SMEM_BYTES (C1_W_OFF * 4 + 450 * 8 + 64)

__global__ __launch_bounds__(256, 7) void conv1_kernel(const float* __restrict__ x,
                                                       const float* __restrict__ w1,
                                                       const float* __restrict__ b1) {
    extern __shared__ float sm1[];
    float* S = sm1;                          // [3][35][67]
    ull* Wp = (ull*)(sm1 + C1_W_OFF);        // [450] packed-dup weights (8B-aligned)
    float* Bias = (float*)(Wp + 450);

    const int b = blockIdx.z;
    const int ox0 = blockIdx.x * 32, oy0 = blockIdx.y * 16;
    const int tid = threadIdx.x;
    const int tx = tid & 15, ty = tid >> 4;

    for (int i = tid; i < 450; i += 256) { ull p; BPACK(p, w1[i]); Wp[i] = p; }
    if (tid < 6) Bias[tid] = b1[tid];

    const int iy0 = oy0 * 2 - 1, ix0 = ox0 * 2 - 1;
    const float* xb = x + (size_t)b * C1_IN * H_IN * H_IN;

#pragma unroll 4
    for (int idx = tid; idx < C1_S_ELEMS; idx += 256) {
        int c = idx / (C1_ROWS * C1_PITCH), r = idx % (C1_ROWS * C1_PITCH);
        int y = r / C1_PITCH, u = r % C1_PITCH;
        int iy = iy0 + y, ix = ix0 + u;
        float v = 0.f;
        if (iy >= 0 && iy < H_IN && ix >= 0 && ix < H_IN)
            v = xb[(c * H_IN + iy) * H_IN + ix];
        S[idx] = v;
    }
    __syncthreads();

    ull acc[6];                              // (px@tx, px@tx+16) per oc
#pragma unroll
    for (int oc = 0; oc < 6; oc++) acc[oc] = 0ULL;

#pragma unroll
    for (int c = 0; c < 3; c++) {
        const float* Sc = S + c * C1_ROWS * C1_PITCH;
#pragma unroll
        for (int ky = 0; ky < 5; ky++) {
            const float* r0 = Sc + (ty * 2 + ky) * C1_PITCH;
#pragma unroll
            for (int kx = 0; kx < 5; kx++) {
                float s0 = r0[tx * 2 + kx];
                float s1 = r0[tx * 2 + 32 + kx];
                ull sp; PACK2(sp, s0, s1);
                const ull* wp = &Wp[(c * 5 + ky) * 5 + kx];
#pragma unroll
                for (int oc = 0; oc < 6; oc++)
                    FMA2(acc[oc], sp, wp[oc * 75]);
            }
        }
    }

    const int oy = oy0 + ty;
    const int oxA = ox0 + tx, oxB = ox0 + tx + 16;
    if (oy < C1_H) {
#pragma unroll
        for (int oc = 0; oc < 6; oc++) {
            __half* dst = g_conv1 + ((size_t)(b * C1_OUT + oc) * C1_H + oy) * C1_H;
            float bias = Bias[oc];
            if (oxA < C1_H) dst[oxA] = __float2half(fmaxf(LO(acc[oc]) + bias, 0.f));
            if (oxB < C1_H) dst[oxB] = __float2half(fmaxf(HI(acc[oc]) + bias, 0.f));
        }
    }
}

// ---------------------------------------------------------------------------
// conv2: maxpool(2,s1) fused into smem load (fp16 src); 6->15, 3x3, s2, pad 1,
// ReLU. OCCUPANCY-FIRST: tile 32x16, pitch-65 smem ~54.8KB -> 4 blocks/SM
// (32 warps, was 16). Thread = 2 y-split px * 15 oc. (fp32 weights, no ull)
// ---------------------------------------------------------------------------
#define C2_PITCH 65
#define C2_ROWS 33
#define C2_P_ELEMS (6 * C2_ROWS * C2_PITCH)        // 12870
#define C2_SMEM_BYTES (C2_P_ELEMS * 4 + 810 * 4 + 15 * 4 + 32)

__global__ __launch_bounds__(256, 4) void conv2_kernel(const float* __restrict__ w2,
                                                       const float* __restrict__ b2) {
    extern __shared__ float sm2[];
    float* P = sm2;                          // [6][33][65]
    float* W = sm2 + C2_P_ELEMS;             // [15][6][3][3]
    float* Bias = W + 810;

    const int b = blockIdx.z;
    const int ox0 = blockIdx.x * 32, oy0 = blockIdx.y * 16;
    const int tid = threadIdx.x;
    const int tx = tid & 31, ty = tid >> 5;  // 32 x 8

    for (int i = tid; i < 810; i += 256) W[i] = w2[i];
    if (tid < 15) Bias[tid] = b2[tid];

    const int py0 = oy0 * 2 - 1, px0 = ox0 * 2 - 1;
    const __half* cb = g_conv1 + (size_t)b * C1_OUT * C1_H * C1_H;

#pragma unroll 4
    for (int idx = tid; idx < C2_P_ELEMS; idx += 256) {
        int c = idx / (C2_ROWS * C2_PITCH), r = idx % (C2_ROWS * C2_PITCH);
        int y = r / C2_PITCH, u = r % C2_PITCH;
        int py = py0 + y, px = px0 + u;
        float v = 0.f;
        if (py >= 0 && py < P1_H && px >= 0 && px < P1_H) {
            const __half* p = cb + (c * C1_H + py) * C1_H + px;
            float v00 = __half2float(p[0]),     v01 = __half2float(p[1]);
            float v10 = __half2float(p[C1_H]),  v11 = __half2float(p[C1_H + 1]);
            v = fmaxf(fmaxf(v00, v01), fmaxf(v10, v11));
        }
        P[idx] = v;
    }
    __syncthreads();

    float acc[2][15];
#pragma unroll
    for (int p = 0; p < 2; p++)
#pragma unroll
        for (int oc = 0; oc < 15; oc++) acc[p][oc] = 0.f;

#pragma unroll
    for (int c = 0; c < 6; c++) {
        const float* Pc = P + c * C2_ROWS * C2_PITCH;
#pragma unroll
        for (int ky = 0; ky < 3; ky++) {
            const float* r0 = Pc + (ty * 2 + ky) * C2_PITCH;
            const float* r1 = Pc + ((ty + 8) * 2 + ky) * C2_PITCH;
#pragma unroll
            for (int kx = 0; kx < 3; kx++) {
                float s0 = r0[tx * 2 + kx];
                float s1 = r1[tx * 2 + kx];
#pragma unroll
                for (int oc = 0; oc < 15; oc++) {
                    float w = W[((oc * 6 + c) * 3 + ky) * 3 + kx];
                    acc[0][oc] += s0 * w;
                    acc[1][oc] += s1 * w;
                }
            }
        }
    }

    const int ox = ox0 + tx;
    const int oyA = oy0 + ty, oyB = oy0 + ty + 8;
    if (ox < C2_H) {
#pragma unroll
        for (int oc = 0; oc < 15; oc++) {
            __half* dst = g_conv2 + (size_t)(b * C2_OUT + oc) * C2_H * C2_H;
            float bias = Bias[oc];
            if (oyA < C2_H) dst[oyA * C2_H + ox] = __float2half(fmaxf(acc[0][oc] + bias, 0.f));
            if (oyB < C2_H) dst[oyB * C2_H + ox] = __float2half(fmaxf(acc[1][oc] + bias, 0.f));
        }
    }
}

// ---------------------------------------------------------------------------
// FC1 via tensor cores (IDENTICAL to round-6 480us version).
// ---------------------------------------------------------------------------
#define FC1_BM 128
#define FC1_BK 16

#define LDSM_X4(r0, r1, r2, r3, addr) \
    asm volatile("ldmatrix.sync.aligned.m8n8.x4.shared.b16 {%0,%1,%2,%3}, [%4];" \
        : "=r"(r0), "=r"(r1), "=r"(r2), "=r"(r3) : "r"(addr))

#define LDSM_X2_T(r0, r1, addr) \
    asm volatile("ldmatrix.sync.aligned.m8n8.x2.trans.shared.b16 {%0,%1}, [%2];" \
        : "=r"(r0), "=r"(r1) : "r"(addr))

#define MMA_16816(c, a0, a1, a2, a3, b0, b1) \
    asm volatile("mma.sync.aligned.m16n8k16.row.col.f32.f16.f16.f32 " \
        "{%0,%1,%2,%3}, {%4,%5,%6,%7}, {%8,%9}, {%0,%1,%2,%3};" \
        : "+f"(c[0]), "+f"(c[1]), "+f"(c[2]), "+f"(c[3]) \
        : "r"(a0), "r"(a1), "r"(a2), "r"(a3), "r"(b0), "r"(b1))

__global__ __launch_bounds__(256) void fc1_mma_kernel(const float* __restrict__ fc1_w) {
    __shared__ __half As[FC1_BM][24];
    __shared__ __half Bs[FC1_BK][136];

    const int tid = threadIdx.x;
    const int lane = tid & 31, w = tid >> 5;
    const int m0 = blockIdx.x * FC1_BM;
    const int k0 = blockIdx.y * KCHUNK;
    const int kend = min(k0 + KCHUNK, K_FC1);

    float acc[15][4];
#pragma unroll
    for (int nt = 0; nt < 15; nt++)
#pragma unroll
        for (int i = 0; i < 4; i++) acc[nt][i] = 0.f;

    const int arow = tid >> 1;
    const int akk = (tid & 1) * 8;
    const int mrow = m0 + arow;

    __half ra[8];
    float rb[8];

    auto loadA = [&](int kb) {
        int k = kb + akk;
        int c = k / 3721;
        int rem = k - c * 3721;
        int y = rem / 61;
        int xx = rem - y * 61;
#pragma unroll
        for (int i = 0; i < 8; i++) {
            float v = 0.f;
            if (k + i < kend) {
                const __half* p = g_conv2 +
                    ((size_t)(mrow * C2_OUT + c) * C2_H + y) * C2_H + xx;
                float v00 = __half2float(p[0]),     v01 = __half2float(p[1]);
                float v10 = __half2float(p[C2_H]),  v11 = __half2float(p[C2_H + 1]);
                v = fmaxf(fmaxf(v00, v01), fmaxf(v10, v11));
            }
            ra[i] = __float2half(v);
            if (++xx == 61) { xx = 0; if (++y == 61) { y = 0; ++c; } }
        }
    };
    auto loadB = [&](int kb) {
#pragma unroll
        for (int i = 0; i < 8; i++) {
            int idx = tid + i * 256;
            rb[i] = 0.f;
            if (idx < 1920) {
                int n = idx >> 4;
                int kk = idx & 15;
                int k = kb + kk;
                if (k < kend) rb[i] = fc1_w[(size_t)n * K_FC1 + k];
            }
        }
    };
    auto stsAB = [&]() {
        uint4 av;
        __half2* ah = (__half2*)&av;
        ah[0] = __halves2half2(ra[0], ra[1]);
        ah[1] = __halves2half2(ra[2], ra[3]);
        ah[2] = __halves2half2(ra[4], ra[5]);
        ah[3] = __halves2half2(ra[6], ra[7]);
        *(uint4*)&As[arow][akk] = av;
#pragma unroll
        for (int i = 0; i < 8; i++) {
            int idx = tid + i * 256;
            if (idx < 1920) Bs[idx & 15][idx >> 4] = __float2half(rb[i]);
        }
    };

    const unsigned aaddr = (unsigned)__cvta_generic_to_shared(
        &As[w * 16 + (lane & 15)][(lane >> 4) * 8]);
    const unsigned baddr0 = (unsigned)__cvta_generic_to_shared(
        &Bs[lane & 15][0]);

    loadA(k0);
    loadB(k0);

    for (int kb = k0; kb < kend; kb += FC1_BK) {
        stsAB();
        __syncthreads();
        if (kb + FC1_BK < kend) { loadA(kb + FC1_BK); loadB(kb + FC1_BK); }

        unsigned a0, a1, a2, a3;
        LDSM_X4(a0, a1, a2, a3, aaddr);
#pragma unroll
        for (int nt = 0; nt < 15; nt++) {
            unsigned b0, b1;
            LDSM_X2_T(b0, b1, baddr0 + nt * 16);
            MMA_16816(acc[nt], a0, a1, a2, a3, b0, b1);
        }
        __syncthreads();
    }

    const int r0 = m0 + w * 16 + (lane >> 2);
    const int cb = (lane & 3) * 2;
    float* dst = g_fc1_part[blockIdx.y];
#pragma unroll
    for (int nt = 0; nt < 15; nt++) {
        int cc = nt * 8 + cb;
        dst[r0 * N_FC1 + cc]           = acc[nt][0];
        dst[r0 * N_FC1 + cc + 1]       = acc[nt][1];
        dst[(r0 + 8) * N_FC1 + cc]     = acc[nt][2];
        dst[(r0 + 8) * N_FC1 + cc + 1] = acc[nt][3];
    }
}

// ---------------------------------------------------------------------------
// Head (identical): reduce partials, FC2, FC3, quantum sim, softmax.
// ---------------------------------------------------------------------------
__global__ void head_kernel(const float* __restrict__ fc1_b,
                            const float* __restrict__ fc2_w,
                            const float* __restrict__ fc2_b,
                            const float* __restrict__ fc3_w,
                            const float* __restrict__ fc3_b,
                            const float* __restrict__ qw,
                            float* __restrict__ out) {
    const int b = blockIdx.x;
    __shared__ float h1[N_FC1];
    __shared__ float h2[N_FC2];
    __shared__ float ang[4];
    const int t = threadIdx.x;

    if (t < N_FC1) {
        float s = fc1_b[t];
#pragma unroll 16
        for (int j = 0; j < KSPLIT; j++) s += g_fc1_part[j][b * N_FC1 + t];
        h1[t] = fmaxf(s, 0.f);
    }
    __syncthreads();

    if (t < N_FC2) {
        float a = fc2_b[t];
#pragma unroll 8
        for (int k = 0; k < N_FC1; k++) a += h1[k] * fc2_w[t * N_FC1 + k];
        h2[t] = fmaxf(a, 0.f);
    }
    __syncthreads();

    if (t < 4) {
        float a = fc3_b[t];
#pragma unroll 4
        for (int k = 0; k < N_FC2; k++) a += h2[k] * fc3_w[t * N_FC2 + k];
        ang[t] = a;
    }
    __syncthreads();

    if (t == 0) {
        float sr[16], si[16];
#pragma unroll
        for (int i = 0; i < 16; i++) { sr[i] = 0.f; si[i] = 0.f; }
        sr[0] = 1.f;

#pragma unroll
        for (int q = 0; q < 4; q++) {
            float th = ang[q] * 0.5f;
            float c = cosf(th), s = sinf(th);
            const int bit = 1 << (3 - q);
#pragma unroll
            for (int i0 = 0; i0 < 16; i0++) {
                if (i0 & bit) continue;
                int i1 = i0 | bit;
                float a0r = sr[i0], a0i = si[i0], a1r = sr[i1], a1i = si[i1];
                sr[i0] = c * a0r + s * a1i;  si[i0] = c * a0i - s * a1r;
                sr[i1] = c * a1r + s * a0i;  si[i1] = c * a1i - s * a0r;
            }
        }
        int w = 0;
#pragma unroll
        for (int d = 0; d < 2; d++) {
#pragma unroll
            for (int q = 0; q < 4; q++) {
                float th = qw[w++] * 0.5f;
                float c = cosf(th), s = sinf(th);
                const int bit = 1 << (3 - q);
#pragma unroll
                for (int i0 = 0; i0 < 16; i0++) {
                    if (i0 & bit) continue;
                    int i1 = i0 | bit;
                    float a0r = sr[i0], a0i = si[i0], a1r = sr[i1], a1i = si[i1];
                    sr[i0] = c * a0r - s * a1r;  si[i0] = c * a0i - s * a1i;
                    sr[i1] = s * a0r + c * a1r;  si[i1] = s * a0i + c * a1i;
                }
            }
#pragma unroll
            for (int q = 0; q < 3; q++) {
                const int m1 = 1 << (3 - q), m2 = 1 << (2 - q);
#pragma unroll
                for (int i = 0; i < 16; i++)
                    if ((i & m1) && (i & m2)) { sr[i] = -sr[i]; si[i] = -si[i]; }
            }
        }
        float l0 = 0.f, l1 = 0.f;
#pragma unroll
        for (int i = 0; i < 16; i++) {
            float p = sr[i] * sr[i] + si[i] * si[i];
            l0 += (i & 8) ? -p : p;
            l1 += (i & 4) ? -p : p;
        }
        float m = fmaxf(l0, l1);
        float e0 = __expf(l0 - m), e1 = __expf(l1 - m);
        float inv = 1.f / (e0 + e1);
        out[b * 2 + 0] = e0 * inv;
        out[b * 2 + 1] = e1 * inv;
    }
}

// ---------------------------------------------------------------------------
extern "C" void kernel_launch(void* const* d_in, const int* in_sizes, int n_in,
                              void* d_out, int out_size) {
    const float* x     = (const float*)d_in[0];
    const float* w1    = (const float*)d_in[1];
    const float* b1    = (const float*)d_in[2];
    const float* w2    = (const float*)d_in[3];
    const float* b2    = (const float*)d_in[4];
    const float* fc1_w = (const float*)d_in[5];
    const float* fc1_b = (const float*)d_in[6];
    const float* fc2_w = (const float*)d_in[7];
    const float* fc2_b = (const float*)d_in[8];
    const float* fc3_w = (const float*)d_in[9];
    const float* fc3_b = (const float*)d_in[10];
    const float* qw    = (const float*)d_in[11];
    float* out = (float*)d_out;

    cudaFuncSetAttribute(conv1_kernel, cudaFuncAttributeMaxDynamicSharedMemorySize, C1_SMEM_BYTES);
    cudaFuncSetAttribute(conv2_kernel, cudaFuncAttributeMaxDynamicSharedMemorySize, C2_SMEM_BYTES);

    conv1_kernel<<<dim3(4, 8, BATCH), 256, C1_SMEM_BYTES>>>(x, w1, b1);
    conv2_kernel<<<dim3(2, 4, BATCH), 256, C2_SMEM_BYTES>>>(w2, b2);
    fc1_mma_kernel<<<dim3(2, KSPLIT), 256>>>(fc1_w);
    head_kernel<<<BATCH, 128>>>(fc1_b, fc2_w, fc2_b, fc3_w, fc3_b, qw, out);
}

// round 9
// speedup vs baseline: 1.4744x; 1.0048x over previous
#include <cuda_runtime.h>
#include <cuda_fp16.h>
#include <math.h>

#define BATCH 256
#define C1_IN 3
#define C1_OUT 6
#define H_IN 250
#define C1_H 124          // conv1 out H/W
#define P1_H 123          // pool1 out H/W
#define C2_OUT 15
#define C2_H 62           // conv2 out H/W
#define P2_H 61           // pool2 out H/W
#define K_FC1 55815       // 15*61*61
#define N_FC1 120
#define N_FC2 84
#define KSPLIT 148
#define KCHUNK 378        // ceil(55815/148)

typedef unsigned long long ull;

// Scratch (static device globals — allocation-free)
__device__ __half g_conv1[(size_t)BATCH * C1_OUT * C1_H * C1_H];   // 47.2 MB
__device__ __half g_conv2[(size_t)BATCH * C2_OUT * C2_H * C2_H];   // 29.5 MB
__device__ float  g_fc1_part[KSPLIT][BATCH * N_FC1];               // 18.2 MB

// packed f32x2 helpers
#define BPACK(dst, f) asm("mov.b64 %0, {%1, %1};" : "=l"(dst) : "r"(__float_as_uint(f)))
#define PACK2(dst, lo, hi) asm("mov.b64 %0, {%1, %2};" : "=l"(dst) : "r"(__float_as_uint(lo)), "r"(__float_as_uint(hi)))
#define FMA2(acc, a, b) asm("fma.rn.f32x2 %0, %1, %2, %0;" : "+l"(acc) : "l"(a), "l"(b))
#define LO(v) __uint_as_float((unsigned)((v) & 0xffffffffULL))
#define HI(v) __uint_as_float((unsigned)((v) >> 32))

// ---------------------------------------------------------------------------
// conv1: IDENTICAL to round-8 411us version. 32x16 tile, 7 blocks/SM.
// ---------------------------------------------------------------------------
#define C1_PITCH 67
#define C1_ROWS 35
#define C1_S_ELEMS (3 * C1_ROWS * C1_PITCH)        // 7035 (odd!)
#define C1_W_OFF 7036                               // even -> 8B-aligned ull*
#define C1_SMEM_BYTES (C1_W_OFF * 4 + 450 * 8 + 64)

__global__ __launch_bounds__(256, 7) void conv1_kernel(const float* __restrict__ x,
                                                       const float* __restrict__ w1,
                                                       const float* __restrict__ b1) {
    extern __shared__ float sm1[];
    float* S = sm1;                          // [3][35][67]
    ull* Wp = (ull*)(sm1 + C1_W_OFF);        // [450]
    float* Bias = (float*)(Wp + 450);

    const int b = blockIdx.z;
    const int ox0 = blockIdx.x * 32, oy0 = blockIdx.y * 16;
    const int tid = threadIdx.x;
    const int tx = tid & 15, ty = tid >> 4;

    for (int i = tid; i < 450; i += 256) { ull p; BPACK(p, w1[i]); Wp[i] = p; }
    if (tid < 6) Bias[tid] = b1[tid];

    const int iy0 = oy0 * 2 - 1, ix0 = ox0 * 2 - 1;
    const float* xb = x + (size_t)b * C1_IN * H_IN * H_IN;

#pragma unroll 4
    for (int idx = tid; idx < C1_S_ELEMS; idx += 256) {
        int c = idx / (C1_ROWS * C1_PITCH), r = idx % (C1_ROWS * C1_PITCH);
        int y = r / C1_PITCH, u = r % C1_PITCH;
        int iy = iy0 + y, ix = ix0 + u;
        float v = 0.f;
        if (iy >= 0 && iy < H_IN && ix >= 0 && ix < H_IN)
            v = xb[(c * H_IN + iy) * H_IN + ix];
        S[idx] = v;
    }
    __syncthreads();

    ull acc[6];
#pragma unroll
    for (int oc = 0; oc < 6; oc++) acc[oc] = 0ULL;

#pragma unroll
    for (int c = 0; c < 3; c++) {
        const float* Sc = S + c * C1_ROWS * C1_PITCH;
#pragma unroll
        for (int ky = 0; ky < 5; ky++) {
            const float* r0 = Sc + (ty * 2 + ky) * C1_PITCH;
#pragma unroll
            for (int kx = 0; kx < 5; kx++) {
                float s0 = r0[tx * 2 + kx];
                float s1 = r0[tx * 2 + 32 + kx];
                ull sp; PACK2(sp, s0, s1);
                const ull* wp = &Wp[(c * 5 + ky) * 5 + kx];
#pragma unroll
                for (int oc = 0; oc < 6; oc++)
                    FMA2(acc[oc], sp, wp[oc * 75]);
            }
        }
    }

    const int oy = oy0 + ty;
    const int oxA = ox0 + tx, oxB = ox0 + tx + 16;
    if (oy < C1_H) {
#pragma unroll
        for (int oc = 0; oc < 6; oc++) {
            __half* dst = g_conv1 + ((size_t)(b * C1_OUT + oc) * C1_H + oy) * C1_H;
            float bias = Bias[oc];
            if (oxA < C1_H) dst[oxA] = __float2half(fmaxf(LO(acc[oc]) + bias, 0.f));
            if (oxB < C1_H) dst[oxB] = __float2half(fmaxf(HI(acc[oc]) + bias, 0.f));
        }
    }
}

// ---------------------------------------------------------------------------
// conv2 v9: fp16 pooled tile + f32x2-PACKED weights (FMA-pipe cycles halve).
// Tile 32x16, 2 y-split px * 15 oc per thread, packed-pair accumulators.
// smem layout: Wp ull[810] FIRST (8B aligned), then P_h half[6*35*68], Bias.
// ---------------------------------------------------------------------------
#define C2_PITCH 68
#define C2_ROWS 35
#define C2_P_ELEMS (6 * C2_ROWS * C2_PITCH)        // 14280 halves
#define C2_SMEM_BYTES (810 * 8 + C2_P_ELEMS * 2 + 64)

__global__ __launch_bounds__(256, 4) void conv2_kernel(const float* __restrict__ w2,
                                                       const float* __restrict__ b2) {
    extern __shared__ ull sm2u[];
    ull* Wp = sm2u;                            // [810] packed-dup weights
    __half* P = (__half*)(sm2u + 810);         // [6][35][68]
    float* Bias = (float*)((char*)P + C2_P_ELEMS * 2);

    const int b = blockIdx.z;
    const int ox0 = blockIdx.x * 32, oy0 = blockIdx.y * 16;
    const int tid = threadIdx.x;
    const int tx = tid & 31, ty = tid >> 5;    // 32 x 8

    for (int i = tid; i < 810; i += 256) { ull p; BPACK(p, w2[i]); Wp[i] = p; }
    if (tid < 15) Bias[tid] = b2[tid];

    const int py0 = oy0 * 2 - 1, px0 = ox0 * 2 - 1;
    const __half* cb = g_conv1 + (size_t)b * C1_OUT * C1_H * C1_H;

#pragma unroll 4
    for (int idx = tid; idx < C2_P_ELEMS; idx += 256) {
        int c = idx / (C2_ROWS * C2_PITCH), r = idx % (C2_ROWS * C2_PITCH);
        int y = r / C2_PITCH, u = r % C2_PITCH;
        int py = py0 + y, px = px0 + u;
        float v = 0.f;
        if (u < 67 && py >= 0 && py < P1_H && px >= 0 && px < P1_H) {
            const __half* p = cb + (c * C1_H + py) * C1_H + px;
            float v00 = __half2float(p[0]),     v01 = __half2float(p[1]);
            float v10 = __half2float(p[C1_H]),  v11 = __half2float(p[C1_H + 1]);
            v = fmaxf(fmaxf(v00, v01), fmaxf(v10, v11));
        }
        P[idx] = __float2half(v);
    }
    __syncthreads();

    ull acc[15];                               // (px@row ty, px@row ty+8) per oc
#pragma unroll
    for (int oc = 0; oc < 15; oc++) acc[oc] = 0ULL;

#pragma unroll
    for (int c = 0; c < 6; c++) {
        const __half* Pc = P + c * C2_ROWS * C2_PITCH;
#pragma unroll
        for (int ky = 0; ky < 3; ky++) {
            const __half* r0 = Pc + (ty * 2 + ky) * C2_PITCH;
            const __half* r1 = Pc + ((ty + 8) * 2 + ky) * C2_PITCH;
#pragma unroll
            for (int kx = 0; kx < 3; kx++) {
                float s0 = __half2float(r0[tx * 2 + kx]);
                float s1 = __half2float(r1[tx * 2 + kx]);
                ull sp; PACK2(sp, s0, s1);
                const ull* wp = &Wp[c * 9 + ky * 3 + kx];
#pragma unroll
                for (int oc = 0; oc < 15; oc++)
                    FMA2(acc[oc], sp, wp[oc * 54]);
            }
        }
    }

    const int ox = ox0 + tx;
    const int oyA = oy0 + ty, oyB = oy0 + ty + 8;
    if (ox < C2_H) {
#pragma unroll
        for (int oc = 0; oc < 15; oc++) {
            __half* dst = g_conv2 + (size_t)(b * C2_OUT + oc) * C2_H * C2_H;
            float bias = Bias[oc];
            if (oyA < C2_H) dst[oyA * C2_H + ox] = __float2half(fmaxf(LO(acc[oc]) + bias, 0.f));
            if (oyB < C2_H) dst[oyB * C2_H + ox] = __float2half(fmaxf(HI(acc[oc]) + bias, 0.f));
        }
    }
}

// ---------------------------------------------------------------------------
// FC1 tensor-core GEMM v9: loadA remapped so warp lanes read CONSECUTIVE k
// (consecutive xx in g_conv2) for one m-row -> 1-2 L1 lines per LDG instead
// of 16-32. KSPLIT 148 -> 296 blocks = 2/SM for latency hiding.
// ---------------------------------------------------------------------------
#define FC1_BM 128
#define FC1_BK 16

#define LDSM_X4(r0, r1, r2, r3, addr) \
    asm volatile("ldmatrix.sync.aligned.m8n8.x4.shared.b16 {%0,%1,%2,%3}, [%4];" \
        : "=r"(r0), "=r"(r1), "=r"(r2), "=r"(r3) : "r"(addr))

#define LDSM_X2_T(r0, r1, addr) \
    asm volatile("ldmatrix.sync.aligned.m8n8.x2.trans.shared.b16 {%0,%1}, [%2];" \
        : "=r"(r0), "=r"(r1) : "r"(addr))

#define MMA_16816(c, a0, a1, a2, a3, b0, b1) \
    asm volatile("mma.sync.aligned.m16n8k16.row.col.f32.f16.f16.f32 " \
        "{%0,%1,%2,%3}, {%4,%5,%6,%7}, {%8,%9}, {%0,%1,%2,%3};" \
        : "+f"(c[0]), "+f"(c[1]), "+f"(c[2]), "+f"(c[3]) \
        : "r"(a0), "r"(a1), "r"(a2), "r"(a3), "r"(b0), "r"(b1))

__global__ __launch_bounds__(256) void fc1_mma_kernel(const float* __restrict__ fc1_w) {
    __shared__ __half As[FC1_BM][24];
    __shared__ __half Bs[FC1_BK][136];

    const int tid = threadIdx.x;
    const int lane = tid & 31, w = tid >> 5;
    const int m0 = blockIdx.x * FC1_BM;
    const int k0 = blockIdx.y * KCHUNK;
    const int kend = min(k0 + KCHUNK, K_FC1);

    float acc[15][4];
#pragma unroll
    for (int nt = 0; nt < 15; nt++)
#pragma unroll
        for (int i = 0; i < 4; i++) acc[nt][i] = 0.f;

    // A loader mapping: kk = tid&15 (consecutive lanes -> consecutive k),
    // rows rbase + 16*i. Coalesced: lanes hit consecutive xx in g_conv2.
    const int kk_a = tid & 15;
    const int rbase = tid >> 4;

    __half ra[8];
    float rb[8];

    auto loadA = [&](int kb) {
        int k = kb + kk_a;
        if (k < kend) {
            int c = k / 3721;
            int rem = k - c * 3721;
            int y = rem / 61;
            int xx = rem - y * 61;
            const __half* base = g_conv2 + ((size_t)c * C2_H + y) * C2_H + xx;
#pragma unroll
            for (int i = 0; i < 8; i++) {
                int mrow = m0 + rbase + 16 * i;
                const __half* p = base + (size_t)mrow * (C2_OUT * C2_H * C2_H);
                float v00 = __half2float(p[0]),     v01 = __half2float(p[1]);
                float v10 = __half2float(p[C2_H]),  v11 = __half2float(p[C2_H + 1]);
                ra[i] = __float2half(fmaxf(fmaxf(v00, v01), fmaxf(v10, v11)));
            }
        } else {
#pragma unroll
            for (int i = 0; i < 8; i++) ra[i] = __float2half(0.f);
        }
    };
    auto loadB = [&](int kb) {
#pragma unroll
        for (int i = 0; i < 8; i++) {
            int idx = tid + i * 256;
            rb[i] = 0.f;
            if (idx < 1920) {
                int n = idx >> 4;
                int kk = idx & 15;
                int k = kb + kk;
                if (k < kend) rb[i] = fc1_w[(size_t)n * K_FC1 + k];
            }
        }
    };
    auto stsAB = [&]() {
#pragma unroll
        for (int i = 0; i < 8; i++)
            As[rbase + 16 * i][kk_a] = ra[i];
#pragma unroll
        for (int i = 0; i < 8; i++) {
            int idx = tid + i * 256;
            if (idx < 1920) Bs[idx & 15][idx >> 4] = __float2half(rb[i]);
        }
    };

    const unsigned aaddr = (unsigned)__cvta_generic_to_shared(
        &As[w * 16 + (lane & 15)][(lane >> 4) * 8]);
    const unsigned baddr0 = (unsigned)__cvta_generic_to_shared(
        &Bs[lane & 15][0]);

    loadA(k0);
    loadB(k0);

    for (int kb = k0; kb < kend; kb += FC1_BK) {
        stsAB();
        __syncthreads();
        if (kb + FC1_BK < kend) { loadA(kb + FC1_BK); loadB(kb + FC1_BK); }

        unsigned a0, a1, a2, a3;
        LDSM_X4(a0, a1, a2, a3, aaddr);
#pragma unroll
        for (int nt = 0; nt < 15; nt++) {
            unsigned b0, b1;
            LDSM_X2_T(b0, b1, baddr0 + nt * 16);
            MMA_16816(acc[nt], a0, a1, a2, a3, b0, b1);
        }
        __syncthreads();
    }

    const int r0 = m0 + w * 16 + (lane >> 2);
    const int cb = (lane & 3) * 2;
    float* dst = g_fc1_part[blockIdx.y];
#pragma unroll
    for (int nt = 0; nt < 15; nt++) {
        int cc = nt * 8 + cb;
        dst[r0 * N_FC1 + cc]           = acc[nt][0];
        dst[r0 * N_FC1 + cc + 1]       = acc[nt][1];
        dst[(r0 + 8) * N_FC1 + cc]     = acc[nt][2];
        dst[(r0 + 8) * N_FC1 + cc + 1] = acc[nt][3];
    }
}

// ---------------------------------------------------------------------------
// Head (identical structure, KSPLIT=148 reduce).
// ---------------------------------------------------------------------------
__global__ void head_kernel(const float* __restrict__ fc1_b,
                            const float* __restrict__ fc2_w,
                            const float* __restrict__ fc2_b,
                            const float* __restrict__ fc3_w,
                            const float* __restrict__ fc3_b,
                            const float* __restrict__ qw,
                            float* __restrict__ out) {
    const int b = blockIdx.x;
    __shared__ float h1[N_FC1];
    __shared__ float h2[N_FC2];
    __shared__ float ang[4];
    const int t = threadIdx.x;

    if (t < N_FC1) {
        float s = fc1_b[t];
#pragma unroll 4
        for (int j = 0; j < KSPLIT; j++) s += g_fc1_part[j][b * N_FC1 + t];
        h1[t] = fmaxf(s, 0.f);
    }
    __syncthreads();

    if (t < N_FC2) {
        float a = fc2_b[t];
#pragma unroll 8
        for (int k = 0; k < N_FC1; k++) a += h1[k] * fc2_w[t * N_FC1 + k];
        h2[t] = fmaxf(a, 0.f);
    }
    __syncthreads();

    if (t < 4) {
        float a = fc3_b[t];
#pragma unroll 4
        for (int k = 0; k < N_FC2; k++) a += h2[k] * fc3_w[t * N_FC2 + k];
        ang[t] = a;
    }
    __syncthreads();

    if (t == 0) {
        float sr[16], si[16];
#pragma unroll
        for (int i = 0; i < 16; i++) { sr[i] = 0.f; si[i] = 0.f; }
        sr[0] = 1.f;

#pragma unroll
        for (int q = 0; q < 4; q++) {
            float th = ang[q] * 0.5f;
            float c = cosf(th), s = sinf(th);
            const int bit = 1 << (3 - q);
#pragma unroll
            for (int i0 = 0; i0 < 16; i0++) {
                if (i0 & bit) continue;
                int i1 = i0 | bit;
                float a0r = sr[i0], a0i = si[i0], a1r = sr[i1], a1i = si[i1];
                sr[i0] = c * a0r + s * a1i;  si[i0] = c * a0i - s * a1r;
                sr[i1] = c * a1r + s * a0i;  si[i1] = c * a1i - s * a0r;
            }
        }
        int w = 0;
#pragma unroll
        for (int d = 0; d < 2; d++) {
#pragma unroll
            for (int q = 0; q < 4; q++) {
                float th = qw[w++] * 0.5f;
                float c = cosf(th), s = sinf(th);
                const int bit = 1 << (3 - q);
#pragma unroll
                for (int i0 = 0; i0 < 16; i0++) {
                    if (i0 & bit) continue;
                    int i1 = i0 | bit;
                    float a0r = sr[i0], a0i = si[i0], a1r = sr[i1], a1i = si[i1];
                    sr[i0] = c * a0r - s * a1r;  si[i0] = c * a0i - s * a1i;
                    sr[i1] = s * a0r + c * a1r;  si[i1] = s * a0i + c * a1i;
                }
            }
#pragma unroll
            for (int q = 0; q < 3; q++) {
                const int m1 = 1 << (3 - q), m2 = 1 << (2 - q);
#pragma unroll
                for (int i = 0; i < 16; i++)
                    if ((i & m1) && (i & m2)) { sr[i] = -sr[i]; si[i] = -si[i]; }
            }
        }
        float l0 = 0.f, l1 = 0.f;
#pragma unroll
        for (int i = 0; i < 16; i++) {
            float p = sr[i] * sr[i] + si[i] * si[i];
            l0 += (i & 8) ? -p : p;
            l1 += (i & 4) ? -p : p;
        }
        float m = fmaxf(l0, l1);
        float e0 = __expf(l0 - m), e1 = __expf(l1 - m);
        float inv = 1.f / (e0 + e1);
        out[b * 2 + 0] = e0 * inv;
        out[b * 2 + 1] = e1 * inv;
    }
}

// ---------------------------------------------------------------------------
extern "C" void kernel_launch(void* const* d_in, const int* in_sizes, int n_in,
                              void* d_out, int out_size) {
    const float* x     = (const float*)d_in[0];
    const float* w1    = (const float*)d_in[1];
    const float* b1    = (const float*)d_in[2];
    const float* w2    = (const float*)d_in[3];
    const float* b2    = (const float*)d_in[4];
    const float* fc1_w = (const float*)d_in[5];
    const float* fc1_b = (const float*)d_in[6];
    const float* fc2_w = (const float*)d_in[7];
    const float* fc2_b = (const float*)d_in[8];
    const float* fc3_w = (const float*)d_in[9];
    const float* fc3_b = (const float*)d_in[10];
    const float* qw    = (const float*)d_in[11];
    float* out = (float*)d_out;

    cudaFuncSetAttribute(conv1_kernel, cudaFuncAttributeMaxDynamicSharedMemorySize, C1_SMEM_BYTES);
    cudaFuncSetAttribute(conv2_kernel, cudaFuncAttributeMaxDynamicSharedMemorySize, C2_SMEM_BYTES);

    conv1_kernel<<<dim3(4, 8, BATCH), 256, C1_SMEM_BYTES>>>(x, w1, b1);
    conv2_kernel<<<dim3(2, 4, BATCH), 256, C2_SMEM_BYTES>>>(w2, b2);
    fc1_mma_kernel<<<dim3(2, KSPLIT), 256>>>(fc1_w);
    head_kernel<<<BATCH, 128>>>(fc1_b, fc2_w, fc2_b, fc3_w, fc3_b, qw, out);
}

// round 10
// speedup vs baseline: 1.5773x; 1.0698x over previous
#include <cuda_runtime.h>
#include <cuda_fp16.h>
#include <math.h>

#define BATCH 256
#define C1_IN 3
#define C1_OUT 6
#define H_IN 250
#define C1_H 124          // conv1 out H/W
#define P1_H 123          // pool1 out H/W
#define C2_OUT 15
#define C2_H 62           // conv2 out H/W
#define P2_H 61           // pool2 out H/W
#define K_FC1 55815       // 15*61*61
#define N_FC1 120
#define N_FC2 84
#define KSPLIT 148
#define KCHUNK 378        // ceil(55815/148)

typedef unsigned long long ull;

// Scratch (static device globals — allocation-free)
__device__ __half g_conv1[(size_t)BATCH * C1_OUT * C1_H * C1_H];   // 47.2 MB
__device__ __half g_conv2[(size_t)BATCH * C2_OUT * C2_H * C2_H];   // 29.5 MB
__device__ float  g_fc1_part[KSPLIT][BATCH * N_FC1];               // 18.2 MB
__device__ float  g_h1[BATCH * N_FC1];                              // 120 KB

// packed f32x2 helpers
#define BPACK(dst, f) asm("mov.b64 %0, {%1, %1};" : "=l"(dst) : "r"(__float_as_uint(f)))
#define PACK2(dst, lo, hi) asm("mov.b64 %0, {%1, %2};" : "=l"(dst) : "r"(__float_as_uint(lo)), "r"(__float_as_uint(hi)))
#define FMA2(acc, a, b) asm("fma.rn.f32x2 %0, %1, %2, %0;" : "+l"(acc) : "l"(a), "l"(b))
#define LO(v) __uint_as_float((unsigned)((v) & 0xffffffffULL))
#define HI(v) __uint_as_float((unsigned)((v) >> 32))

// ---------------------------------------------------------------------------
// conv1 v10: bank-conflict-free via even/odd-x de-interleaved smem planes.
// s-access u = 2*tx+kx -> plane[kx&1], index tx+(kx>>1) (+16 for the +32 px).
// Plane pitch 40 floats: 2 rows apart = 80 floats = +16 banks -> the two
// half-warps (rows ty*2 and ty*2+2) occupy disjoint bank halves. 6 blocks/SM.
// ---------------------------------------------------------------------------
#define C1_PP 40                               // plane pitch (floats)
#define C1_PLANE (3 * C1_ROWS_ * C1_PP)        // 4200 floats per plane
#define C1_ROWS_ 35
#define C1_W_OFF (2 * C1_PLANE)                // 8400 (even -> 8B-aligned ull*)
#define C1_SMEM_BYTES (C1_W_OFF * 4 + 450 * 8 + 64)

__global__ __launch_bounds__(256, 6) void conv1_kernel(const float* __restrict__ x,
                                                       const float* __restrict__ w1,
                                                       const float* __restrict__ b1) {
    extern __shared__ float sm1[];
    // planes: even-x at sm1[0], odd-x at sm1[C1_PLANE]
    ull* Wp = (ull*)(sm1 + C1_W_OFF);          // [450]
    float* Bias = (float*)(Wp + 450);

    const int b = blockIdx.z;
    const int ox0 = blockIdx.x * 32, oy0 = blockIdx.y * 16;
    const int tid = threadIdx.x;
    const int tx = tid & 15, ty = tid >> 4;

    for (int i = tid; i < 450; i += 256) { ull p; BPACK(p, w1[i]); Wp[i] = p; }
    if (tid < 6) Bias[tid] = b1[tid];

    const int iy0 = oy0 * 2 - 1, ix0 = ox0 * 2 - 1;
    const float* xb = x + (size_t)b * C1_IN * H_IN * H_IN;

#pragma unroll 4
    for (int idx = tid; idx < 3 * C1_ROWS_ * 67; idx += 256) {
        int c = idx / (C1_ROWS_ * 67), r = idx % (C1_ROWS_ * 67);
        int y = r / 67, u = r % 67;
        int iy = iy0 + y, ix = ix0 + u;
        float v = 0.f;
        if (iy >= 0 && iy < H_IN && ix >= 0 && ix < H_IN)
            v = xb[(c * H_IN + iy) * H_IN + ix];
        sm1[(u & 1) * C1_PLANE + (c * C1_ROWS_ + y) * C1_PP + (u >> 1)] = v;
    }
    __syncthreads();

    ull acc[6];
#pragma unroll
    for (int oc = 0; oc < 6; oc++) acc[oc] = 0ULL;

#pragma unroll
    for (int c = 0; c < 3; c++) {
#pragma unroll
        for (int ky = 0; ky < 5; ky++) {
            const float* re = sm1 + (c * C1_ROWS_ + ty * 2 + ky) * C1_PP;
            const float* ro = re + C1_PLANE;
#pragma unroll
            for (int kx = 0; kx < 5; kx++) {
                const float* pl = (kx & 1) ? ro : re;
                int j = tx + (kx >> 1);
                float s0 = pl[j];
                float s1 = pl[j + 16];
                ull sp; PACK2(sp, s0, s1);
                const ull* wp = &Wp[(c * 5 + ky) * 5 + kx];
#pragma unroll
                for (int oc = 0; oc < 6; oc++)
                    FMA2(acc[oc], sp, wp[oc * 75]);
            }
        }
    }

    const int oy = oy0 + ty;
    const int oxA = ox0 + tx, oxB = ox0 + tx + 16;
    if (oy < C1_H) {
#pragma unroll
        for (int oc = 0; oc < 6; oc++) {
            __half* dst = g_conv1 + ((size_t)(b * C1_OUT + oc) * C1_H + oy) * C1_H;
            float bias = Bias[oc];
            if (oxA < C1_H) dst[oxA] = __float2half(fmaxf(LO(acc[oc]) + bias, 0.f));
            if (oxB < C1_H) dst[oxB] = __float2half(fmaxf(HI(acc[oc]) + bias, 0.f));
        }
    }
}

// ---------------------------------------------------------------------------
// conv2: IDENTICAL to round-9. fp16 pooled tile + f32x2 packed weights.
// ---------------------------------------------------------------------------
#define C2_PITCH 68
#define C2_ROWS 35
#define C2_P_ELEMS (6 * C2_ROWS * C2_PITCH)
#define C2_SMEM_BYTES (810 * 8 + C2_P_ELEMS * 2 + 64)

__global__ __launch_bounds__(256, 4) void conv2_kernel(const float* __restrict__ w2,
                                                       const float* __restrict__ b2) {
    extern __shared__ ull sm2u[];
    ull* Wp = sm2u;                            // [810]
    __half* P = (__half*)(sm2u + 810);         // [6][35][68]
    float* Bias = (float*)((char*)P + C2_P_ELEMS * 2);

    const int b = blockIdx.z;
    const int ox0 = blockIdx.x * 32, oy0 = blockIdx.y * 16;
    const int tid = threadIdx.x;
    const int tx = tid & 31, ty = tid >> 5;

    for (int i = tid; i < 810; i += 256) { ull p; BPACK(p, w2[i]); Wp[i] = p; }
    if (tid < 15) Bias[tid] = b2[tid];

    const int py0 = oy0 * 2 - 1, px0 = ox0 * 2 - 1;
    const __half* cb = g_conv1 + (size_t)b * C1_OUT * C1_H * C1_H;

#pragma unroll 4
    for (int idx = tid; idx < C2_P_ELEMS; idx += 256) {
        int c = idx / (C2_ROWS * C2_PITCH), r = idx % (C2_ROWS * C2_PITCH);
        int y = r / C2_PITCH, u = r % C2_PITCH;
        int py = py0 + y, px = px0 + u;
        float v = 0.f;
        if (u < 67 && py >= 0 && py < P1_H && px >= 0 && px < P1_H) {
            const __half* p = cb + (c * C1_H + py) * C1_H + px;
            float v00 = __half2float(p[0]),     v01 = __half2float(p[1]);
            float v10 = __half2float(p[C1_H]),  v11 = __half2float(p[C1_H + 1]);
            v = fmaxf(fmaxf(v00, v01), fmaxf(v10, v11));
        }
        P[idx] = __float2half(v);
    }
    __syncthreads();

    ull acc[15];
#pragma unroll
    for (int oc = 0; oc < 15; oc++) acc[oc] = 0ULL;

#pragma unroll
    for (int c = 0; c < 6; c++) {
        const __half* Pc = P + c * C2_ROWS * C2_PITCH;
#pragma unroll
        for (int ky = 0; ky < 3; ky++) {
            const __half* r0 = Pc + (ty * 2 + ky) * C2_PITCH;
            const __half* r1 = Pc + ((ty + 8) * 2 + ky) * C2_PITCH;
#pragma unroll
            for (int kx = 0; kx < 3; kx++) {
                float s0 = __half2float(r0[tx * 2 + kx]);
                float s1 = __half2float(r1[tx * 2 + kx]);
                ull sp; PACK2(sp, s0, s1);
                const ull* wp = &Wp[c * 9 + ky * 3 + kx];
#pragma unroll
                for (int oc = 0; oc < 15; oc++)
                    FMA2(acc[oc], sp, wp[oc * 54]);
            }
        }
    }

    const int ox = ox0 + tx;
    const int oyA = oy0 + ty, oyB = oy0 + ty + 8;
    if (ox < C2_H) {
#pragma unroll
        for (int oc = 0; oc < 15; oc++) {
            __half* dst = g_conv2 + (size_t)(b * C2_OUT + oc) * C2_H * C2_H;
            float bias = Bias[oc];
            if (oyA < C2_H) dst[oyA * C2_H + ox] = __float2half(fmaxf(LO(acc[oc]) + bias, 0.f));
            if (oyB < C2_H) dst[oyB * C2_H + ox] = __float2half(fmaxf(HI(acc[oc]) + bias, 0.f));
        }
    }
}

// ---------------------------------------------------------------------------
// FC1 tensor-core GEMM: IDENTICAL to round-9 (coalesced loadA, KSPLIT=148).
// ---------------------------------------------------------------------------
#define FC1_BM 128
#define FC1_BK 16

#define LDSM_X4(r0, r1, r2, r3, addr) \
    asm volatile("ldmatrix.sync.aligned.m8n8.x4.shared.b16 {%0,%1,%2,%3}, [%4];" \
        : "=r"(r0), "=r"(r1), "=r"(r2), "=r"(r3) : "r"(addr))

#define LDSM_X2_T(r0, r1, addr) \
    asm volatile("ldmatrix.sync.aligned.m8n8.x2.trans.shared.b16 {%0,%1}, [%2];" \
        : "=r"(r0), "=r"(r1) : "r"(addr))

#define MMA_16816(c, a0, a1, a2, a3, b0, b1) \
    asm volatile("mma.sync.aligned.m16n8k16.row.col.f32.f16.f16.f32 " \
        "{%0,%1,%2,%3}, {%4,%5,%6,%7}, {%8,%9}, {%0,%1,%2,%3};" \
        : "+f"(c[0]), "+f"(c[1]), "+f"(c[2]), "+f"(c[3]) \
        : "r"(a0), "r"(a1), "r"(a2), "r"(a3), "r"(b0), "r"(b1))

__global__ __launch_bounds__(256) void fc1_mma_kernel(const float* __restrict__ fc1_w) {
    __shared__ __half As[FC1_BM][24];
    __shared__ __half Bs[FC1_BK][136];

    const int tid = threadIdx.x;
    const int lane = tid & 31, w = tid >> 5;
    const int m0 = blockIdx.x * FC1_BM;
    const int k0 = blockIdx.y * KCHUNK;
    const int kend = min(k0 + KCHUNK, K_FC1);

    float acc[15][4];
#pragma unroll
    for (int nt = 0; nt < 15; nt++)
#pragma unroll
        for (int i = 0; i < 4; i++) acc[nt][i] = 0.f;

    const int kk_a = tid & 15;
    const int rbase = tid >> 4;

    __half ra[8];
    float rb[8];

    auto loadA = [&](int kb) {
        int k = kb + kk_a;
        if (k < kend) {
            int c = k / 3721;
            int rem = k - c * 3721;
            int y = rem / 61;
            int xx = rem - y * 61;
            const __half* base = g_conv2 + ((size_t)c * C2_H + y) * C2_H + xx;
#pragma unroll
            for (int i = 0; i < 8; i++) {
                int mrow = m0 + rbase + 16 * i;
                const __half* p = base + (size_t)mrow * (C2_OUT * C2_H * C2_H);
                float v00 = __half2float(p[0]),     v01 = __half2float(p[1]);
                float v10 = __half2float(p[C2_H]),  v11 = __half2float(p[C2_H + 1]);
                ra[i] = __float2half(fmaxf(fmaxf(v00, v01), fmaxf(v10, v11)));
            }
        } else {
#pragma unroll
            for (int i = 0; i < 8; i++) ra[i] = __float2half(0.f);
        }
    };
    auto loadB = [&](int kb) {
#pragma unroll
        for (int i = 0; i < 8; i++) {
            int idx = tid + i * 256;
            rb[i] = 0.f;
            if (idx < 1920) {
                int n = idx >> 4;
                int kk = idx & 15;
                int k = kb + kk;
                if (k < kend) rb[i] = fc1_w[(size_t)n * K_FC1 + k];
            }
        }
    };
    auto stsAB = [&]() {
#pragma unroll
        for (int i = 0; i < 8; i++)
            As[rbase + 16 * i][kk_a] = ra[i];
#pragma unroll
        for (int i = 0; i < 8; i++) {
            int idx = tid + i * 256;
            if (idx < 1920) Bs[idx & 15][idx >> 4] = __float2half(rb[i]);
        }
    };

    const unsigned aaddr = (unsigned)__cvta_generic_to_shared(
        &As[w * 16 + (lane & 15)][(lane >> 4) * 8]);
    const unsigned baddr0 = (unsigned)__cvta_generic_to_shared(
        &Bs[lane & 15][0]);

    loadA(k0);
    loadB(k0);

    for (int kb = k0; kb < kend; kb += FC1_BK) {
        stsAB();
        __syncthreads();
        if (kb + FC1_BK < kend) { loadA(kb + FC1_BK); loadB(kb + FC1_BK); }

        unsigned a0, a1, a2, a3;
        LDSM_X4(a0, a1, a2, a3, aaddr);
#pragma unroll
        for (int nt = 0; nt < 15; nt++) {
            unsigned b0, b1;
            LDSM_X2_T(b0, b1, baddr0 + nt * 16);
            MMA_16816(acc[nt], a0, a1, a2, a3, b0, b1);
        }
        __syncthreads();
    }

    const int r0 = m0 + w * 16 + (lane >> 2);
    const int cb = (lane & 3) * 2;
    float* dst = g_fc1_part[blockIdx.y];
#pragma unroll
    for (int nt = 0; nt < 15; nt++) {
        int cc = nt * 8 + cb;
        dst[r0 * N_FC1 + cc]           = acc[nt][0];
        dst[r0 * N_FC1 + cc + 1]       = acc[nt][1];
        dst[(r0 + 8) * N_FC1 + cc]     = acc[nt][2];
        dst[(r0 + 8) * N_FC1 + cc + 1] = acc[nt][3];
    }
}

// ---------------------------------------------------------------------------
// reduce_kernel v10: coalesced KSPLIT reduction + bias + ReLU -> g_h1.
// 120 blocks x 256 threads = 30720 threads, 1 output each; consecutive
// threads read consecutive addresses in every partial slab (full coalescing),
// unroll-8 for MLP. ~18.2 MB at near-peak BW.
// ---------------------------------------------------------------------------
__global__ __launch_bounds__(256) void reduce_kernel(const float* __restrict__ fc1_b) {
    const int idx = blockIdx.x * 256 + threadIdx.x;        // 0..30719
    float s = fc1_b[idx % N_FC1];
#pragma unroll 8
    for (int j = 0; j < KSPLIT; j++)
        s += g_fc1_part[j][idx];
    g_h1[idx] = fmaxf(s, 0.f);
}

// ---------------------------------------------------------------------------
// Head v10: reads precomputed h1; FC2+ReLU, FC3, quantum sim, softmax.
// ---------------------------------------------------------------------------
__global__ void head_kernel(const float* __restrict__ fc2_w,
                            const float* __restrict__ fc2_b,
                            const float* __restrict__ fc3_w,
                            const float* __restrict__ fc3_b,
                            const float* __restrict__ qw,
                            float* __restrict__ out) {
    const int b = blockIdx.x;
    __shared__ float h1[N_FC1];
    __shared__ float h2[N_FC2];
    __shared__ float ang[4];
    const int t = threadIdx.x;

    if (t < N_FC1) h1[t] = g_h1[b * N_FC1 + t];
    __syncthreads();

    if (t < N_FC2) {
        float a = fc2_b[t];
#pragma unroll 8
        for (int k = 0; k < N_FC1; k++) a += h1[k] * fc2_w[t * N_FC1 + k];
        h2[t] = fmaxf(a, 0.f);
    }
    __syncthreads();

    if (t < 4) {
        float a = fc3_b[t];
#pragma unroll 4
        for (int k = 0; k < N_FC2; k++) a += h2[k] * fc3_w[t * N_FC2 + k];
        ang[t] = a;
    }
    __syncthreads();

    if (t == 0) {
        float sr[16], si[16];
#pragma unroll
        for (int i = 0; i < 16; i++) { sr[i] = 0.f; si[i] = 0.f; }
        sr[0] = 1.f;

#pragma unroll
        for (int q = 0; q < 4; q++) {
            float th = ang[q] * 0.5f;
            float c = cosf(th), s = sinf(th);
            const int bit = 1 << (3 - q);
#pragma unroll
            for (int i0 = 0; i0 < 16; i0++) {
                if (i0 & bit) continue;
                int i1 = i0 | bit;
                float a0r = sr[i0], a0i = si[i0], a1r = sr[i1], a1i = si[i1];
                sr[i0] = c * a0r + s * a1i;  si[i0] = c * a0i - s * a1r;
                sr[i1] = c * a1r + s * a0i;  si[i1] = c * a1i - s * a0r;
            }
        }
        int w = 0;
#pragma unroll
        for (int d = 0; d < 2; d++) {
#pragma unroll
            for (int q = 0; q < 4; q++) {
                float th = qw[w++] * 0.5f;
                float c = cosf(th), s = sinf(th);
                const int bit = 1 << (3 - q);
#pragma unroll
                for (int i0 = 0; i0 < 16; i0++) {
                    if (i0 & bit) continue;
                    int i1 = i0 | bit;
                    float a0r = sr[i0], a0i = si[i0], a1r = sr[i1], a1i = si[i1];
                    sr[i0] = c * a0r - s * a1r;  si[i0] = c * a0i - s * a1i;
                    sr[i1] = s * a0r + c * a1r;  si[i1] = s * a0i + c * a1i;
                }
            }
#pragma unroll
            for (int q = 0; q < 3; q++) {
                const int m1 = 1 << (3 - q), m2 = 1 << (2 - q);
#pragma unroll
                for (int i = 0; i < 16; i++)
                    if ((i & m1) && (i & m2)) { sr[i] = -sr[i]; si[i] = -si[i]; }
            }
        }
        float l0 = 0.f, l1 = 0.f;
#pragma unroll
        for (int i = 0; i < 16; i++) {
            float p = sr[i] * sr[i] + si[i] * si[i];
            l0 += (i & 8) ? -p : p;
            l1 += (i & 4) ? -p : p;
        }
        float m = fmaxf(l0, l1);
        float e0 = __expf(l0 - m), e1 = __expf(l1 - m);
        float inv = 1.f / (e0 + e1);
        out[b * 2 + 0] = e0 * inv;
        out[b * 2 + 1] = e1 * inv;
    }
}

// ---------------------------------------------------------------------------
extern "C" void kernel_launch(void* const* d_in, const int* in_sizes, int n_in,
                              void* d_out, int out_size) {
    const float* x     = (const float*)d_in[0];
    const float* w1    = (const float*)d_in[1];
    const float* b1    = (const float*)d_in[2];
    const float* w2    = (const float*)d_in[3];
    const float* b2    = (const float*)d_in[4];
    const float* fc1_w = (const float*)d_in[5];
    const float* fc1_b = (const float*)d_in[6];
    const float* fc2_w = (const float*)d_in[7];
    const float* fc2_b = (const float*)d_in[8];
    const float* fc3_w = (const float*)d_in[9];
    const float* fc3_b = (const float*)d_in[10];
    const float* qw    = (const float*)d_in[11];
    float* out = (float*)d_out;

    cudaFuncSetAttribute(conv1_kernel, cudaFuncAttributeMaxDynamicSharedMemorySize, C1_SMEM_BYTES);
    cudaFuncSetAttribute(conv2_kernel, cudaFuncAttributeMaxDynamicSharedMemorySize, C2_SMEM_BYTES);

    conv1_kernel<<<dim3(4, 8, BATCH), 256, C1_SMEM_BYTES>>>(x, w1, b1);
    conv2_kernel<<<dim3(2, 4, BATCH), 256, C2_SMEM_BYTES>>>(w2, b2);
    fc1_mma_kernel<<<dim3(2, KSPLIT), 256>>>(fc1_w);
    reduce_kernel<<<120, 256>>>(fc1_b);
    head_kernel<<<BATCH, 128>>>(fc2_w, fc2_b, fc3_w, fc3_b, qw, out);
}

// round 11
// speedup vs baseline: 1.5830x; 1.0036x over previous
#include <cuda_runtime.h>
#include <cuda_fp16.h>
#include <math.h>

#define BATCH 256
#define C1_IN 3
#define C1_OUT 6
#define H_IN 250
#define C1_H 124          // conv1 out H/W
#define P1_H 123          // pool1 out H/W
#define C2_OUT 15
#define C2_H 62           // conv2 out H/W
#define P2_H 61           // pool2 out H/W
#define K_FC1 55815       // 15*61*61
#define N_FC1 120
#define N_FC2 84
#define KSPLIT 148
#define KCHUNK 378        // ceil(55815/148)

typedef unsigned long long ull;

// Scratch (static device globals — allocation-free)
__device__ __half g_conv1[(size_t)BATCH * C1_OUT * C1_H * C1_H];   // 47.2 MB
__device__ __half g_conv2[(size_t)BATCH * C2_OUT * C2_H * C2_H];   // 29.5 MB
__device__ float  g_fc1_part[KSPLIT][BATCH * N_FC1];               // 18.2 MB
__device__ float  g_h1[BATCH * N_FC1];                              // 120 KB

// packed f32x2 helpers
#define BPACK(dst, f) asm("mov.b64 %0, {%1, %1};" : "=l"(dst) : "r"(__float_as_uint(f)))
#define PACK2(dst, lo, hi) asm("mov.b64 %0, {%1, %2};" : "=l"(dst) : "r"(__float_as_uint(lo)), "r"(__float_as_uint(hi)))
#define FMA2(acc, a, b) asm("fma.rn.f32x2 %0, %1, %2, %0;" : "+l"(acc) : "l"(a), "l"(b))
#define LO(v) __uint_as_float((unsigned)((v) & 0xffffffffULL))
#define HI(v) __uint_as_float((unsigned)((v) >> 32))

// ---------------------------------------------------------------------------
// conv1 v11: de-interleaved even/odd-x planes (bank-conflict-free) +
// TAP-MAJOR packed weights -> 3x LDS.128 per tap (was 6x LDS.64).
// ---------------------------------------------------------------------------
#define C1_PP 40
#define C1_ROWS_ 35
#define C1_PLANE (3 * C1_ROWS_ * C1_PP)        // 4200
#define C1_W_OFF (2 * C1_PLANE)                // 8400 floats -> 16B-aligned
#define C1_SMEM_BYTES (C1_W_OFF * 4 + 450 * 8 + 64)

__global__ __launch_bounds__(256, 6) void conv1_kernel(const float* __restrict__ x,
                                                       const float* __restrict__ w1,
                                                       const float* __restrict__ b1) {
    extern __shared__ float sm1[];
    ull* Wp = (ull*)(sm1 + C1_W_OFF);          // [75 taps][6 oc]
    float* Bias = (float*)(Wp + 450);

    const int b = blockIdx.z;
    const int ox0 = blockIdx.x * 32, oy0 = blockIdx.y * 16;
    const int tid = threadIdx.x;
    const int tx = tid & 15, ty = tid >> 4;

    // tap-major: Wp[tap*6 + oc] = dup(w1[oc*75 + tap])
    for (int i = tid; i < 450; i += 256) {
        ull p; BPACK(p, w1[(i % 6) * 75 + (i / 6)]);
        Wp[i] = p;
    }
    if (tid < 6) Bias[tid] = b1[tid];

    const int iy0 = oy0 * 2 - 1, ix0 = ox0 * 2 - 1;
    const float* xb = x + (size_t)b * C1_IN * H_IN * H_IN;

#pragma unroll 4
    for (int idx = tid; idx < 3 * C1_ROWS_ * 67; idx += 256) {
        int c = idx / (C1_ROWS_ * 67), r = idx % (C1_ROWS_ * 67);
        int y = r / 67, u = r % 67;
        int iy = iy0 + y, ix = ix0 + u;
        float v = 0.f;
        if (iy >= 0 && iy < H_IN && ix >= 0 && ix < H_IN)
            v = xb[(c * H_IN + iy) * H_IN + ix];
        sm1[(u & 1) * C1_PLANE + (c * C1_ROWS_ + y) * C1_PP + (u >> 1)] = v;
    }
    __syncthreads();

    ull acc[6];
#pragma unroll
    for (int oc = 0; oc < 6; oc++) acc[oc] = 0ULL;

#pragma unroll
    for (int c = 0; c < 3; c++) {
#pragma unroll
        for (int ky = 0; ky < 5; ky++) {
            const float* re = sm1 + (c * C1_ROWS_ + ty * 2 + ky) * C1_PP;
            const float* ro = re + C1_PLANE;
#pragma unroll
            for (int kx = 0; kx < 5; kx++) {
                const float* pl = (kx & 1) ? ro : re;
                int j = tx + (kx >> 1);
                float s0 = pl[j];
                float s1 = pl[j + 16];
                ull sp; PACK2(sp, s0, s1);
                const ulonglong2* wv =
                    (const ulonglong2*)(Wp + ((c * 5 + ky) * 5 + kx) * 6);
                ulonglong2 wa = wv[0], wb = wv[1], wc = wv[2];
                FMA2(acc[0], sp, wa.x); FMA2(acc[1], sp, wa.y);
                FMA2(acc[2], sp, wb.x); FMA2(acc[3], sp, wb.y);
                FMA2(acc[4], sp, wc.x); FMA2(acc[5], sp, wc.y);
            }
        }
    }

    const int oy = oy0 + ty;
    const int oxA = ox0 + tx, oxB = ox0 + tx + 16;
    if (oy < C1_H) {
#pragma unroll
        for (int oc = 0; oc < 6; oc++) {
            __half* dst = g_conv1 + ((size_t)(b * C1_OUT + oc) * C1_H + oy) * C1_H;
            float bias = Bias[oc];
            if (oxA < C1_H) dst[oxA] = __float2half(fmaxf(LO(acc[oc]) + bias, 0.f));
            if (oxB < C1_H) dst[oxB] = __float2half(fmaxf(HI(acc[oc]) + bias, 0.f));
        }
    }
}

// ---------------------------------------------------------------------------
// conv2 v11: fp16 pooled tile + TAP-MAJOR packed weights (16-ull padded) ->
// 7x LDS.128 + 1x LDS.64 per tap (was 15x LDS.64).
// ---------------------------------------------------------------------------
#define C2_PITCH 68
#define C2_ROWS 35
#define C2_P_ELEMS (6 * C2_ROWS * C2_PITCH)
#define C2_W_ULL (54 * 16)                     // 864 padded slots
#define C2_SMEM_BYTES (C2_W_ULL * 8 + C2_P_ELEMS * 2 + 64)

__global__ __launch_bounds__(256, 4) void conv2_kernel(const float* __restrict__ w2,
                                                       const float* __restrict__ b2) {
    extern __shared__ ull sm2u[];
    ull* Wp = sm2u;                            // [54 taps][16 slots (15 oc)]
    __half* P = (__half*)(sm2u + C2_W_ULL);    // [6][35][68]
    float* Bias = (float*)((char*)P + C2_P_ELEMS * 2);

    const int b = blockIdx.z;
    const int ox0 = blockIdx.x * 32, oy0 = blockIdx.y * 16;
    const int tid = threadIdx.x;
    const int tx = tid & 31, ty = tid >> 5;

    for (int i = tid; i < C2_W_ULL; i += 256) {
        int oc = i & 15, tap = i >> 4;
        float v = (oc < 15) ? w2[oc * 54 + tap] : 0.f;
        ull p; BPACK(p, v);
        Wp[i] = p;
    }
    if (tid < 15) Bias[tid] = b2[tid];

    const int py0 = oy0 * 2 - 1, px0 = ox0 * 2 - 1;
    const __half* cb = g_conv1 + (size_t)b * C1_OUT * C1_H * C1_H;

#pragma unroll 4
    for (int idx = tid; idx < C2_P_ELEMS; idx += 256) {
        int c = idx / (C2_ROWS * C2_PITCH), r = idx % (C2_ROWS * C2_PITCH);
        int y = r / C2_PITCH, u = r % C2_PITCH;
        int py = py0 + y, px = px0 + u;
        float v = 0.f;
        if (u < 67 && py >= 0 && py < P1_H && px >= 0 && px < P1_H) {
            const __half* p = cb + (c * C1_H + py) * C1_H + px;
            float v00 = __half2float(p[0]),     v01 = __half2float(p[1]);
            float v10 = __half2float(p[C1_H]),  v11 = __half2float(p[C1_H + 1]);
            v = fmaxf(fmaxf(v00, v01), fmaxf(v10, v11));
        }
        P[idx] = __float2half(v);
    }
    __syncthreads();

    ull acc[15];
#pragma unroll
    for (int oc = 0; oc < 15; oc++) acc[oc] = 0ULL;

#pragma unroll
    for (int c = 0; c < 6; c++) {
        const __half* Pc = P + c * C2_ROWS * C2_PITCH;
#pragma unroll
        for (int ky = 0; ky < 3; ky++) {
            const __half* r0 = Pc + (ty * 2 + ky) * C2_PITCH;
            const __half* r1 = Pc + ((ty + 8) * 2 + ky) * C2_PITCH;
#pragma unroll
            for (int kx = 0; kx < 3; kx++) {
                float s0 = __half2float(r0[tx * 2 + kx]);
                float s1 = __half2float(r1[tx * 2 + kx]);
                ull sp; PACK2(sp, s0, s1);
                const ull* wt = Wp + (c * 9 + ky * 3 + kx) * 16;
                const ulonglong2* wv = (const ulonglong2*)wt;
                ulonglong2 wA = wv[0], wB = wv[1], wC = wv[2], wD = wv[3];
                ulonglong2 wE = wv[4], wF = wv[5], wG = wv[6];
                ull w14 = wt[14];
                FMA2(acc[0], sp, wA.x);  FMA2(acc[1], sp, wA.y);
                FMA2(acc[2], sp, wB.x);  FMA2(acc[3], sp, wB.y);
                FMA2(acc[4], sp, wC.x);  FMA2(acc[5], sp, wC.y);
                FMA2(acc[6], sp, wD.x);  FMA2(acc[7], sp, wD.y);
                FMA2(acc[8], sp, wE.x);  FMA2(acc[9], sp, wE.y);
                FMA2(acc[10], sp, wF.x); FMA2(acc[11], sp, wF.y);
                FMA2(acc[12], sp, wG.x); FMA2(acc[13], sp, wG.y);
                FMA2(acc[14], sp, w14);
            }
        }
    }

    const int ox = ox0 + tx;
    const int oyA = oy0 + ty, oyB = oy0 + ty + 8;
    if (ox < C2_H) {
#pragma unroll
        for (int oc = 0; oc < 15; oc++) {
            __half* dst = g_conv2 + (size_t)(b * C2_OUT + oc) * C2_H * C2_H;
            float bias = Bias[oc];
            if (oyA < C2_H) dst[oyA * C2_H + ox] = __float2half(fmaxf(LO(acc[oc]) + bias, 0.f));
            if (oyB < C2_H) dst[oyB * C2_H + ox] = __float2half(fmaxf(HI(acc[oc]) + bias, 0.f));
        }
    }
}

// ---------------------------------------------------------------------------
// FC1 tensor-core GEMM v11: BM=256 (512 threads, 16 warps, grid = KSPLIT) ->
// B matrix streamed ONCE (was twice). Coalesced A gather, split-K partials.
// ---------------------------------------------------------------------------
#define FC1_BK 16

#define LDSM_X4(r0, r1, r2, r3, addr) \
    asm volatile("ldmatrix.sync.aligned.m8n8.x4.shared.b16 {%0,%1,%2,%3}, [%4];" \
        : "=r"(r0), "=r"(r1), "=r"(r2), "=r"(r3) : "r"(addr))

#define LDSM_X2_T(r0, r1, addr) \
    asm volatile("ldmatrix.sync.aligned.m8n8.x2.trans.shared.b16 {%0,%1}, [%2];" \
        : "=r"(r0), "=r"(r1) : "r"(addr))

#define MMA_16816(c, a0, a1, a2, a3, b0, b1) \
    asm volatile("mma.sync.aligned.m16n8k16.row.col.f32.f16.f16.f32 " \
        "{%0,%1,%2,%3}, {%4,%5,%6,%7}, {%8,%9}, {%0,%1,%2,%3};" \
        : "+f"(c[0]), "+f"(c[1]), "+f"(c[2]), "+f"(c[3]) \
        : "r"(a0), "r"(a1), "r"(a2), "r"(a3), "r"(b0), "r"(b1))

__global__ __launch_bounds__(512) void fc1_mma_kernel(const float* __restrict__ fc1_w) {
    __shared__ __half As[256][24];
    __shared__ __half Bs[FC1_BK][136];

    const int tid = threadIdx.x;
    const int lane = tid & 31, w = tid >> 5;   // 16 warps, one m16 slab each
    const int k0 = blockIdx.x * KCHUNK;
    const int kend = min(k0 + KCHUNK, K_FC1);

    float acc[15][4];
#pragma unroll
    for (int nt = 0; nt < 15; nt++)
#pragma unroll
        for (int i = 0; i < 4; i++) acc[nt][i] = 0.f;

    const int kk_a = tid & 15;                 // consecutive lanes -> consecutive k
    const int rbase = tid >> 4;                // 0..31

    __half ra[8];
    float rb[4];

    auto loadA = [&](int kb) {
        int k = kb + kk_a;
        if (k < kend) {
            int c = k / 3721;
            int rem = k - c * 3721;
            int y = rem / 61;
            int xx = rem - y * 61;
            const __half* base = g_conv2 + ((size_t)c * C2_H + y) * C2_H + xx;
#pragma unroll
            for (int i = 0; i < 8; i++) {
                int mrow = rbase + 32 * i;
                const __half* p = base + (size_t)mrow * (C2_OUT * C2_H * C2_H);
                float v00 = __half2float(p[0]),     v01 = __half2float(p[1]);
                float v10 = __half2float(p[C2_H]),  v11 = __half2float(p[C2_H + 1]);
                ra[i] = __float2half(fmaxf(fmaxf(v00, v01), fmaxf(v10, v11)));
            }
        } else {
#pragma unroll
            for (int i = 0; i < 8; i++) ra[i] = __float2half(0.f);
        }
    };
    auto loadB = [&](int kb) {
#pragma unroll
        for (int i = 0; i < 4; i++) {
            int idx = tid + i * 512;           // < 1920 always (3.75*512)
            rb[i] = 0.f;
            if (idx < 1920) {
                int n = idx >> 4;
                int kk = idx & 15;
                int k = kb + kk;
                if (k < kend) rb[i] = fc1_w[(size_t)n * K_FC1 + k];
            }
        }
    };
    auto stsAB = [&]() {
#pragma unroll
        for (int i = 0; i < 8; i++)
            As[rbase + 32 * i][kk_a] = ra[i];
#pragma unroll
        for (int i = 0; i < 4; i++) {
            int idx = tid + i * 512;
            if (idx < 1920) Bs[idx & 15][idx >> 4] = __float2half(rb[i]);
        }
    };

    const unsigned aaddr = (unsigned)__cvta_generic_to_shared(
        &As[w * 16 + (lane & 15)][(lane >> 4) * 8]);
    const unsigned baddr0 = (unsigned)__cvta_generic_to_shared(
        &Bs[lane & 15][0]);

    loadA(k0);
    loadB(k0);

    for (int kb = k0; kb < kend; kb += FC1_BK) {
        stsAB();
        __syncthreads();
        if (kb + FC1_BK < kend) { loadA(kb + FC1_BK); loadB(kb + FC1_BK); }

        unsigned a0, a1, a2, a3;
        LDSM_X4(a0, a1, a2, a3, aaddr);
#pragma unroll
        for (int nt = 0; nt < 15; nt++) {
            unsigned b0, b1;
            LDSM_X2_T(b0, b1, baddr0 + nt * 16);
            MMA_16816(acc[nt], a0, a1, a2, a3, b0, b1);
        }
        __syncthreads();
    }

    const int r0 = w * 16 + (lane >> 2);
    const int cb = (lane & 3) * 2;
    float* dst = g_fc1_part[blockIdx.x];
#pragma unroll
    for (int nt = 0; nt < 15; nt++) {
        int cc = nt * 8 + cb;
        dst[r0 * N_FC1 + cc]           = acc[nt][0];
        dst[r0 * N_FC1 + cc + 1]       = acc[nt][1];
        dst[(r0 + 8) * N_FC1 + cc]     = acc[nt][2];
        dst[(r0 + 8) * N_FC1 + cc + 1] = acc[nt][3];
    }
}

// ---------------------------------------------------------------------------
// reduce v11: full-chip grid (240 blocks x 128 thr) + unroll-16 MLP.
// ---------------------------------------------------------------------------
__global__ __launch_bounds__(128) void reduce_kernel(const float* __restrict__ fc1_b) {
    const int idx = blockIdx.x * 128 + threadIdx.x;        // 0..30719
    float s = fc1_b[idx % N_FC1];
#pragma unroll 16
    for (int j = 0; j < KSPLIT; j++)
        s += g_fc1_part[j][idx];
    g_h1[idx] = fmaxf(s, 0.f);
}

// ---------------------------------------------------------------------------
// Head: reads precomputed h1; FC2+ReLU, FC3, quantum sim, softmax.
// ---------------------------------------------------------------------------
__global__ void head_kernel(const float* __restrict__ fc2_w,
                            const float* __restrict__ fc2_b,
                            const float* __restrict__ fc3_w,
                            const float* __restrict__ fc3_b,
                            const float* __restrict__ qw,
                            float* __restrict__ out) {
    const int b = blockIdx.x;
    __shared__ float h1[N_FC1];
    __shared__ float h2[N_FC2];
    __shared__ float ang[4];
    const int t = threadIdx.x;

    if (t < N_FC1) h1[t] = g_h1[b * N_FC1 + t];
    __syncthreads();

    if (t < N_FC2) {
        float a = fc2_b[t];
#pragma unroll 8
        for (int k = 0; k < N_FC1; k++) a += h1[k] * fc2_w[t * N_FC1 + k];
        h2[t] = fmaxf(a, 0.f);
    }
    __syncthreads();

    if (t < 4) {
        float a = fc3_b[t];
#pragma unroll 4
        for (int k = 0; k < N_FC2; k++) a += h2[k] * fc3_w[t * N_FC2 + k];
        ang[t] = a;
    }
    __syncthreads();

    if (t == 0) {
        float sr[16], si[16];
#pragma unroll
        for (int i = 0; i < 16; i++) { sr[i] = 0.f; si[i] = 0.f; }
        sr[0] = 1.f;

#pragma unroll
        for (int q = 0; q < 4; q++) {
            float th = ang[q] * 0.5f;
            float c = cosf(th), s = sinf(th);
            const int bit = 1 << (3 - q);
#pragma unroll
            for (int i0 = 0; i0 < 16; i0++) {
                if (i0 & bit) continue;
                int i1 = i0 | bit;
                float a0r = sr[i0], a0i = si[i0], a1r = sr[i1], a1i = si[i1];
                sr[i0] = c * a0r + s * a1i;  si[i0] = c * a0i - s * a1r;
                sr[i1] = c * a1r + s * a0i;  si[i1] = c * a1i - s * a0r;
            }
        }
        int w = 0;
#pragma unroll
        for (int d = 0; d < 2; d++) {
#pragma unroll
            for (int q = 0; q < 4; q++) {
                float th = qw[w++] * 0.5f;
                float c = cosf(th), s = sinf(th);
                const int bit = 1 << (3 - q);
#pragma unroll
                for (int i0 = 0; i0 < 16; i0++) {
                    if (i0 & bit) continue;
                    int i1 = i0 | bit;
                    float a0r = sr[i0], a0i = si[i0], a1r = sr[i1], a1i = si[i1];
                    sr[i0] = c * a0r - s * a1r;  si[i0] = c * a0i - s * a1i;
                    sr[i1] = s * a0r + c * a1r;  si[i1] = s * a0i + c * a1i;
                }
            }
#pragma unroll
            for (int q = 0; q < 3; q++) {
                const int m1 = 1 << (3 - q), m2 = 1 << (2 - q);
#pragma unroll
                for (int i = 0; i < 16; i++)
                    if ((i & m1) && (i & m2)) { sr[i] = -sr[i]; si[i] = -si[i]; }
            }
        }
        float l0 = 0.f, l1 = 0.f;
#pragma unroll
        for (int i = 0; i < 16; i++) {
            float p = sr[i] * sr[i] + si[i] * si[i];
            l0 += (i & 8) ? -p : p;
            l1 += (i & 4) ? -p : p;
        }
        float m = fmaxf(l0, l1);
        float e0 = __expf(l0 - m), e1 = __expf(l1 - m);
        float inv = 1.f / (e0 + e1);
        out[b * 2 + 0] = e0 * inv;
        out[b * 2 + 1] = e1 * inv;
    }
}

// ---------------------------------------------------------------------------
extern "C" void kernel_launch(void* const* d_in, const int* in_sizes, int n_in,
                              void* d_out, int out_size) {
    const float* x     = (const float*)d_in[0];
    const float* w1    = (const float*)d_in[1];
    const float* b1    = (const float*)d_in[2];
    const float* w2    = (const float*)d_in[3];
    const float* b2    = (const float*)d_in[4];
    const float* fc1_w = (const float*)d_in[5];
    const float* fc1_b = (const float*)d_in[6];
    const float* fc2_w = (const float*)d_in[7];
    const float* fc2_b = (const float*)d_in[8];
    const float* fc3_w = (const float*)d_in[9];
    const float* fc3_b = (const float*)d_in[10];
    const float* qw    = (const float*)d_in[11];
    float* out = (float*)d_out;

    cudaFuncSetAttribute(conv1_kernel, cudaFuncAttributeMaxDynamicSharedMemorySize, C1_SMEM_BYTES);
    cudaFuncSetAttribute(conv2_kernel, cudaFuncAttributeMaxDynamicSharedMemorySize, C2_SMEM_BYTES);

    conv1_kernel<<<dim3(4, 8, BATCH), 256, C1_SMEM_BYTES>>>(x, w1, b1);
    conv2_kernel<<<dim3(2, 4, BATCH), 256, C2_SMEM_BYTES>>>(w2, b2);
    fc1_mma_kernel<<<KSPLIT, 512>>>(fc1_w);
    reduce_kernel<<<240, 128>>>(fc1_b);
    head_kernel<<<BATCH, 128>>>(fc2_w, fc2_b, fc3_w, fc3_b, qw, out);
}